// round 3
// baseline (speedup 1.0000x reference)
#include <cuda_runtime.h>
#include <cuda_bf16.h>

#define BB 32
#define TT 512
#define DD 768
#define HH 512
#define CC 7
#define K2 2048          // gates GEMM K = ctx(768) + xt(768) + h(512)
#define N4H 2048         // 4*H
#define NTASK 128

// ---------------- device state (static scratch; no allocations) ----------------
__device__ float g_enc[BB*TT*HH];          // [b][t][h]  enc_proj
__device__ float g_Wcat[2*K2*N4H];         // [dir][k][jj] transposed/interleaved weights
__device__ float g_bcat[2*N4H];            // [dir][jj]
__device__ float g_WdecT[HH*HH];           // [k][n]
__device__ float g_h[2*BB*HH];
__device__ float g_c[2*BB*HH];
__device__ float g_decp[8*2*BB*HH];        // [kc8][dir][b][n] dec partials
__device__ float g_scores[2*BB*TT];        // [dir][b][t]
__device__ float g_ctxp[4*2*BB*DD];        // [part4][dir][b][d]
__device__ float g_gpart[16*2*BB*N4H];     // [kc16][dir][b][jj]
__device__ float g_hs[2*TT*BB*HH];         // [dir][t][b][h]
__device__ unsigned int g_arrive;

// ---------------- helpers ----------------
__device__ __forceinline__ float tanh_acc(float x){
    // accurate tanh via exp: 1 - 2/(e^{2x}+1). abs err ~1e-7.
    float e = __expf(x + x);
    return 1.0f - __fdividef(2.0f, e + 1.0f);
}
__device__ __forceinline__ float sigm(float x){ return 1.0f/(1.0f+__expf(-x)); }
__device__ __forceinline__ float warpMax(float v){
    #pragma unroll
    for(int o=16;o;o>>=1) v = fmaxf(v, __shfl_xor_sync(0xffffffffu, v, o));
    return v;
}
__device__ __forceinline__ float warpSum(float v){
    #pragma unroll
    for(int o=16;o;o>>=1) v += __shfl_xor_sync(0xffffffffu, v, o);
    return v;
}

// ---------------- grid barrier (monotonic counter, reset by k_init) ------------
__device__ __forceinline__ void gbar(unsigned int target){
    __syncthreads();
    if(threadIdx.x == 0){
        __threadfence();
        atomicAdd(&g_arrive, 1u);
        unsigned int vv;
        do {
            asm volatile("ld.acquire.gpu.u32 %0, [%1];" : "=r"(vv) : "l"(&g_arrive));
        } while(vv < target);
    }
    __syncthreads();
}

// ---------------- init ----------------------------------------------------------
__global__ void k_init(const float* __restrict__ b_dec){
    int i = blockIdx.x*blockDim.x + threadIdx.x;       // grid covers 262144
    if(i == 0) g_arrive = 0u;
    if(i < 2*BB*HH){ g_h[i]=0.f; g_c[i]=0.f; }
    if(i < 8*2*BB*HH){
        int kc = i >> 15;                               // 2*BB*HH = 32768
        g_decp[i] = (kc==0) ? b_dec[i & (HH-1)] : 0.f;
    }
}

// ---------------- weight prep ---------------------------------------------------
__global__ void k_prep(const float* __restrict__ Wf_ih, const float* __restrict__ Wf_hh,
                       const float* __restrict__ bf,
                       const float* __restrict__ Wb_ih, const float* __restrict__ Wb_hh,
                       const float* __restrict__ bb,
                       const float* __restrict__ W_dec){
    int tid0 = blockIdx.x*blockDim.x + threadIdx.x;
    int stride = gridDim.x*blockDim.x;
    // Wcat[dir][k][jj], jj = hcol*4+g, source row j = g*512 + hcol (torch i,f,g,o)
    for(int i = tid0; i < 2*K2*N4H; i += stride){
        int jj = i & (N4H-1);
        int r  = i >> 11;
        int k  = r & (K2-1);
        int dir = r >> 11;
        int j = ((jj&3)<<9) + (jj>>2);
        const float* Wih = dir ? Wb_ih : Wf_ih;
        const float* Whh = dir ? Wb_hh : Wf_hh;
        float vv = (k < 1536) ? Wih[j*1536 + k] : Whh[j*512 + (k-1536)];
        g_Wcat[i] = vv;
    }
    if(tid0 < 2*N4H){
        int jj = tid0 & (N4H-1); int dir = tid0 >> 11;
        int j = ((jj&3)<<9) + (jj>>2);
        g_bcat[tid0] = dir ? bb[j] : bf[j];
    }
    if(tid0 < HH*HH){
        int n = tid0 & (HH-1); int k = tid0 >> 9;
        g_WdecT[k*HH + n] = W_dec[n*HH + k];
    }
}

// ---------------- enc_proj GEMM -------------------------------------------------
__global__ void k_enc_gemm(const float* __restrict__ A, const float* __restrict__ Bm,
                           const float* __restrict__ bias){
    __shared__ float As[16][68];
    __shared__ float Bs[16][68];
    const int Kk = DD, Nn = HH;
    int n0 = blockIdx.x*64, m0 = blockIdx.y*64;
    int tid = threadIdx.x;
    int tm = tid>>4, tn = tid&15;
    float acc[4][4];
    #pragma unroll
    for(int i=0;i<4;i++)
        #pragma unroll
        for(int j=0;j<4;j++) acc[i][j] = bias[n0 + tn*4 + j];

    int lrow = tid>>2, lkq = (tid&3)*4;
    for(int k0=0;k0<Kk;k0+=16){
        float4 av = *(const float4*)&A[(long)(m0+lrow)*Kk + k0 + lkq];
        float4 bv = *(const float4*)&Bm[(long)(n0+lrow)*Kk + k0 + lkq];
        __syncthreads();
        As[lkq+0][lrow]=av.x; As[lkq+1][lrow]=av.y; As[lkq+2][lrow]=av.z; As[lkq+3][lrow]=av.w;
        Bs[lkq+0][lrow]=bv.x; Bs[lkq+1][lrow]=bv.y; Bs[lkq+2][lrow]=bv.z; Bs[lkq+3][lrow]=bv.w;
        __syncthreads();
        #pragma unroll
        for(int kk=0;kk<16;kk++){
            float4 a4 = *(const float4*)&As[kk][tm*4];
            float4 b4 = *(const float4*)&Bs[kk][tn*4];
            float aa[4] = {a4.x,a4.y,a4.z,a4.w};
            float bb4[4] = {b4.x,b4.y,b4.z,b4.w};
            #pragma unroll
            for(int i=0;i<4;i++)
                #pragma unroll
                for(int j=0;j<4;j++) acc[i][j] += aa[i]*bb4[j];
        }
    }
    #pragma unroll
    for(int i=0;i<4;i++)
        #pragma unroll
        for(int j=0;j<4;j++)
            g_enc[(long)(m0+tm*4+i)*Nn + n0 + tn*4 + j] = acc[i][j];
}

// ---------------- persistent recurrent kernel -----------------------------------
union SH {
    struct { float d0[HH], d1[HH], vs[HH]; } a;
    struct { float w0[TT], w1[TT]; float red0[8], red1[8]; } bp;
    struct { float As[16][32]; float Bs[16][512]; } c;
    struct { float Hs[32][64]; float Ws[64][68]; } e;
};

__global__ void __launch_bounds__(256, 1)
k_persist(const float* __restrict__ x, const float* __restrict__ v,
          const float* __restrict__ b_dec, int G){
    __shared__ SH sh;
    const int tid = threadIdx.x;
    const int lane = tid & 31, warp = tid >> 5;
    unsigned int bt = (unsigned)G;     // barrier target

    for(int s=0; s<TT; s++){
        // ======== Phase A: attention scores (needs dec partials) ========
        for(int task = blockIdx.x; task < NTASK; task += G){
            int b = task >> 2, tp = task & 3;
            for(int i = tid; i < HH; i += 256){
                float a0=0.f, a1=0.f;
                #pragma unroll
                for(int kc=0;kc<8;kc++){
                    a0 += g_decp[((kc*2+0)*BB + b)*HH + i];
                    a1 += g_decp[((kc*2+1)*BB + b)*HH + i];
                }
                sh.a.d0[i]=a0; sh.a.d1[i]=a1; sh.a.vs[i]=v[i];
            }
            __syncthreads();
            #pragma unroll 1
            for(int i=0;i<16;i++){
                int t = tp*128 + warp*16 + i;
                const float* e = &g_enc[(b*TT + t)*HH];
                float s0=0.f, s1=0.f;
                #pragma unroll
                for(int j=0;j<16;j++){
                    int h = lane + j*32;
                    float ev = e[h];
                    float vv = sh.a.vs[h];
                    s0 += vv*tanh_acc(ev + sh.a.d0[h]);
                    s1 += vv*tanh_acc(ev + sh.a.d1[h]);
                }
                s0 = warpSum(s0); s1 = warpSum(s1);
                if(lane==0){
                    g_scores[b*TT + t] = s0;
                    g_scores[(BB + b)*TT + t] = s1;
                }
            }
            __syncthreads();
        }
        gbar(bt); bt += G;

        // ======== Phase B: softmax + context partials ========
        for(int task = blockIdx.x; task < NTASK; task += G){
            int b = task >> 2, tp = task & 3;
            float m0=-1e30f, m1=-1e30f;
            for(int i=tid;i<TT;i+=256){
                float a = g_scores[b*TT+i];      sh.bp.w0[i]=a; m0=fmaxf(m0,a);
                float c = g_scores[(BB+b)*TT+i]; sh.bp.w1[i]=c; m1=fmaxf(m1,c);
            }
            m0 = warpMax(m0); m1 = warpMax(m1);
            if(lane==0){ sh.bp.red0[warp]=m0; sh.bp.red1[warp]=m1; }
            __syncthreads();
            m0 = sh.bp.red0[0]; m1 = sh.bp.red1[0];
            #pragma unroll
            for(int j=1;j<8;j++){ m0=fmaxf(m0,sh.bp.red0[j]); m1=fmaxf(m1,sh.bp.red1[j]); }
            __syncthreads();

            float z0=0.f, z1=0.f;
            for(int i=tid;i<TT;i+=256){
                float e0 = __expf(sh.bp.w0[i]-m0); sh.bp.w0[i]=e0; z0+=e0;
                float e1 = __expf(sh.bp.w1[i]-m1); sh.bp.w1[i]=e1; z1+=e1;
            }
            z0 = warpSum(z0); z1 = warpSum(z1);
            if(lane==0){ sh.bp.red0[warp]=z0; sh.bp.red1[warp]=z1; }
            __syncthreads();
            z0 = 0.f; z1 = 0.f;
            #pragma unroll
            for(int j=0;j<8;j++){ z0+=sh.bp.red0[j]; z1+=sh.bp.red1[j]; }
            float inv0 = 1.0f/z0, inv1 = 1.0f/z1;
            __syncthreads();

            float a0[3]={0,0,0}, a1[3]={0,0,0};
            int t0 = tp*128;
            #pragma unroll 2
            for(int t=t0;t<t0+128;t++){
                float ww0 = sh.bp.w0[t]*inv0, ww1 = sh.bp.w1[t]*inv1;
                const float* xr = &x[(long)(b*TT + t)*DD];
                #pragma unroll
                for(int q=0;q<3;q++){
                    float xv = xr[tid + q*256];
                    a0[q] += ww0*xv; a1[q] += ww1*xv;
                }
            }
            #pragma unroll
            for(int q=0;q<3;q++){
                g_ctxp[((tp*2+0)*BB + b)*DD + tid + q*256] = a0[q];
                g_ctxp[((tp*2+1)*BB + b)*DD + tid + q*256] = a1[q];
            }
            __syncthreads();
        }
        gbar(bt); bt += G;

        // ======== Phase C: gates GEMM partials (M32 x N512 x K128 per task) ====
        for(int task = blockIdx.x; task < NTASK; task += G){
            int dir = task & 1, jt = (task>>1)&3, kc = task>>3;
            int n0 = jt*512, k0 = kc*128;
            int t = dir ? (TT-1-s) : s;
            int ty = tid>>6, tx = tid&63;
            float acc[8][8];
            #pragma unroll
            for(int i=0;i<8;i++)
                #pragma unroll
                for(int j=0;j<8;j++) acc[i][j]=0.f;

            for(int kb=0;kb<128;kb+=16){
                __syncthreads();
                // A tile 16k x 32b
                for(int lin=tid; lin<512; lin+=256){
                    int bi = lin&31, kk = lin>>5;
                    int k = k0 + kb + kk;
                    float val;
                    if(k0 < 768){
                        val = g_ctxp[((0*2+dir)*BB+bi)*DD + k]
                            + g_ctxp[((1*2+dir)*BB+bi)*DD + k]
                            + g_ctxp[((2*2+dir)*BB+bi)*DD + k]
                            + g_ctxp[((3*2+dir)*BB+bi)*DD + k];
                    } else if(k0 < 1536){
                        val = x[(long)(bi*TT + t)*DD + (k-768)];
                    } else {
                        val = g_h[(dir*BB+bi)*HH + (k-1536)];
                    }
                    sh.c.As[kk][bi] = val;
                }
                // B tile 16k x 512jj (float4, coalesced)
                const float4* wsrc = (const float4*)&g_Wcat[(long)dir*(K2*N4H) + (long)(k0+kb)*N4H + n0];
                #pragma unroll
                for(int r=0;r<8;r++){
                    int idx = tid + 256*r;
                    int kk = idx>>7, c4 = idx&127;
                    ((float4*)sh.c.Bs[kk])[c4] = wsrc[kk*512 + c4];
                }
                __syncthreads();
                #pragma unroll
                for(int kk=0;kk<16;kk++){
                    float4 a0 = *(const float4*)&sh.c.As[kk][ty*8];
                    float4 a1 = *(const float4*)&sh.c.As[kk][ty*8+4];
                    float4 b0 = *(const float4*)&sh.c.Bs[kk][tx*8];
                    float4 b1 = *(const float4*)&sh.c.Bs[kk][tx*8+4];
                    float av[8] = {a0.x,a0.y,a0.z,a0.w,a1.x,a1.y,a1.z,a1.w};
                    float bv[8] = {b0.x,b0.y,b0.z,b0.w,b1.x,b1.y,b1.z,b1.w};
                    #pragma unroll
                    for(int i=0;i<8;i++)
                        #pragma unroll
                        for(int j=0;j<8;j++) acc[i][j] += av[i]*bv[j];
                }
            }
            #pragma unroll
            for(int i=0;i<8;i++){
                int bi = ty*8 + i;
                float* dst = &g_gpart[((long)(kc*2+dir)*BB + bi)*N4H + n0 + tx*8];
                *(float4*)dst       = make_float4(acc[i][0],acc[i][1],acc[i][2],acc[i][3]);
                *((float4*)dst + 1) = make_float4(acc[i][4],acc[i][5],acc[i][6],acc[i][7]);
            }
            __syncthreads();
        }
        gbar(bt); bt += G;

        // ======== Phase D: LSTM pointwise ========
        for(int idx = blockIdx.x*256 + tid; idx < 2*BB*HH; idx += G*256){
            int hc = idx & (HH-1);
            int b  = (idx>>9) & (BB-1);
            int dir = idx>>14;
            int t = dir ? (TT-1-s) : s;
            float4 gs = make_float4(0.f,0.f,0.f,0.f);
            #pragma unroll
            for(int p=0;p<16;p++){
                float4 gp = *(const float4*)&g_gpart[((long)(p*2+dir)*BB + b)*N4H + hc*4];
                gs.x+=gp.x; gs.y+=gp.y; gs.z+=gp.z; gs.w+=gp.w;
            }
            float4 bc = *(const float4*)&g_bcat[dir*N4H + hc*4];
            float ig = sigm(gs.x+bc.x);
            float fg = sigm(gs.y+bc.y);
            float gg = tanh_acc(gs.z+bc.z);
            float og = sigm(gs.w+bc.w);
            int ix = (dir*BB+b)*HH + hc;
            float c = fg*g_c[ix] + ig*gg;
            float h = og*tanh_acc(c);
            g_c[ix]=c; g_h[ix]=h;
            g_hs[((dir*TT+t)*BB + b)*HH + hc] = h;
        }
        gbar(bt); bt += G;

        // ======== Phase E: dec partials (h @ WdecT), K-split ========
        for(int task = blockIdx.x; task < NTASK; task += G){
            int dir = task & 1, nt = (task>>1)&7, kc = task>>4;
            int n0 = nt*64, k0 = kc*64;
            for(int lin=tid; lin<2048; lin+=256){
                int bi=lin>>6, k=lin&63;
                sh.e.Hs[bi][k] = g_h[(dir*BB+bi)*HH + k0 + k];
            }
            for(int lin=tid; lin<4096; lin+=256){
                int k=lin>>6, n=lin&63;
                sh.e.Ws[k][n] = g_WdecT[(k0+k)*HH + n0 + n];
            }
            __syncthreads();
            int tb = tid>>3, tn = (tid&7)*8;
            float acc[8];
            #pragma unroll
            for(int j=0;j<8;j++) acc[j]=0.f;
            #pragma unroll 4
            for(int k=0;k<64;k++){
                float a = sh.e.Hs[tb][k];
                #pragma unroll
                for(int j=0;j<8;j++) acc[j] += a*sh.e.Ws[k][tn+j];
            }
            #pragma unroll
            for(int j=0;j<8;j++){
                int n = n0 + tn + j;
                float vv = acc[j] + ((kc==0) ? b_dec[n] : 0.f);
                g_decp[((kc*2+dir)*BB + tb)*HH + n] = vv;
            }
            __syncthreads();
        }
        gbar(bt); bt += G;
    }
}

// ---------------- final head ----------------------------------------------------
__global__ void k_head(const float* __restrict__ W_head, const float* __restrict__ b_head,
                       float* __restrict__ out){
    __shared__ float Ws[CC*2*HH];   // 28KB
    int tid = threadIdx.x;
    for(int i=tid;i<CC*2*HH;i+=256) Ws[i] = W_head[i];
    __syncthreads();
    int warp = tid>>5, lane = tid&31;
    int m = blockIdx.x*8 + warp;          // m = b*T + t
    int b = m >> 9, t = m & (TT-1);
    const float* hf = &g_hs[((0*TT+t)*BB + b)*HH];
    const float* hb = &g_hs[((1*TT+t)*BB + b)*HH];
    float acc[CC];
    #pragma unroll
    for(int c=0;c<CC;c++) acc[c]=0.f;
    #pragma unroll 4
    for(int i=0;i<16;i++){
        int k = lane + i*32;
        float vf = hf[k];
        float vb = hb[k];
        #pragma unroll
        for(int c=0;c<CC;c++){
            acc[c] += vf*Ws[c*1024 + k] + vb*Ws[c*1024 + 512 + k];
        }
    }
    float res = 0.f;
    #pragma unroll
    for(int c=0;c<CC;c++){
        float r = warpSum(acc[c]);
        if(lane==c) res = r;
    }
    if(lane < CC) out[m*CC + lane] = res + b_head[lane];
}

// ---------------- launch ----------------
extern "C" void kernel_launch(void* const* d_in, const int* in_sizes, int n_in,
                              void* d_out, int out_size){
    const float* x      = (const float*)d_in[0];
    const float* Wf_ih  = (const float*)d_in[1];
    const float* Wf_hh  = (const float*)d_in[2];
    const float* bf     = (const float*)d_in[3];
    const float* Wb_ih  = (const float*)d_in[4];
    const float* Wb_hh  = (const float*)d_in[5];
    const float* bb     = (const float*)d_in[6];
    const float* W_enc  = (const float*)d_in[7];
    const float* b_enc  = (const float*)d_in[8];
    const float* W_dec  = (const float*)d_in[9];
    const float* b_dec  = (const float*)d_in[10];
    const float* v      = (const float*)d_in[11];
    const float* W_head = (const float*)d_in[12];
    const float* b_head = (const float*)d_in[13];
    float* out = (float*)d_out;

    int dev = 0;
    cudaGetDevice(&dev);
    int nsm = 128;
    cudaDeviceGetAttribute(&nsm, cudaDevAttrMultiProcessorCount, dev);
    int G = nsm;                      // 1 block/SM => co-resident, barrier-safe

    k_init<<<1024, 256>>>(b_dec);
    k_prep<<<2048, 256>>>(Wf_ih, Wf_hh, bf, Wb_ih, Wb_hh, bb, W_dec);
    k_enc_gemm<<<dim3(8, 256), 256>>>(x, W_enc, b_enc);
    k_persist<<<G, 256>>>(x, v, b_dec, G);
    k_head<<<2048, 256>>>(W_head, b_head, out);
}

// round 6
// speedup vs baseline: 1.1104x; 1.1104x over previous
#include <cuda_runtime.h>
#include <cuda_bf16.h>

#define BB 32
#define TT 512
#define DD 768
#define HH 512
#define CC 7
#define K2 2048          // gates GEMM K = ctx(768) + xt(768) + h(512)
#define N4H 2048         // 4*H

// ---------------- device state (static scratch; no allocations) ----------------
__device__ float g_enc[BB*TT*HH];          // [b][t][h]  enc_proj
__device__ float g_Wcat[2*K2*N4H];         // [dir][k][jj] transposed/interleaved weights
__device__ float g_bcat[2*N4H];            // [dir][jj]
__device__ float g_WdecT[HH*HH];           // [k][n]
__device__ float g_h[2*BB*HH];
__device__ float g_c[2*BB*HH];
__device__ float g_decp[8*2*BB*HH];        // [kc8][dir][b][n] dec partials
__device__ float g_scores[2*BB*TT];        // [dir][b][t]
__device__ float g_ctxp[8*2*BB*DD];        // [part8][dir][b][d]
__device__ float g_gpart[16*2*BB*N4H];     // [kc16][dir][b][jj]
__device__ float g_hs[2*TT*BB*HH];         // [dir][t][b][h]
__device__ unsigned int g_arrive;

// ---------------- helpers ----------------
__device__ __forceinline__ float tanh_acc(float x){
    float e = __expf(x + x);
    return 1.0f - __fdividef(2.0f, e + 1.0f);
}
__device__ __forceinline__ float sigm(float x){ return 1.0f/(1.0f+__expf(-x)); }
__device__ __forceinline__ float warpMax(float v){
    #pragma unroll
    for(int o=16;o;o>>=1) v = fmaxf(v, __shfl_xor_sync(0xffffffffu, v, o));
    return v;
}
__device__ __forceinline__ float warpSum(float v){
    #pragma unroll
    for(int o=16;o;o>>=1) v += __shfl_xor_sync(0xffffffffu, v, o);
    return v;
}

// ---------------- grid barrier (monotonic counter, reset by k_init) ------------
__device__ __forceinline__ void gbar(unsigned int target){
    __syncthreads();
    if(threadIdx.x == 0){
        __threadfence();
        atomicAdd(&g_arrive, 1u);
        unsigned int vv;
        unsigned int ns = 64;
        #pragma unroll 1
        do {
            asm volatile("ld.acquire.gpu.u32 %0, [%1];" : "=r"(vv) : "l"(&g_arrive));
            if(vv >= target) break;
            __nanosleep(ns);
            if(ns < 1024) ns <<= 1;
        } while(true);
    }
    __syncthreads();
}

// ---------------- init ----------------------------------------------------------
__global__ void k_init(const float* __restrict__ b_dec){
    int i = blockIdx.x*blockDim.x + threadIdx.x;       // grid covers 262144
    if(i == 0) g_arrive = 0u;
    if(i < 2*BB*HH){ g_h[i]=0.f; g_c[i]=0.f; }
    if(i < 8*2*BB*HH){
        int kc = i >> 15;
        g_decp[i] = (kc==0) ? b_dec[i & (HH-1)] : 0.f;
    }
}

// ---------------- weight prep ---------------------------------------------------
__global__ void k_prep(const float* __restrict__ Wf_ih, const float* __restrict__ Wf_hh,
                       const float* __restrict__ bf,
                       const float* __restrict__ Wb_ih, const float* __restrict__ Wb_hh,
                       const float* __restrict__ bb,
                       const float* __restrict__ W_dec){
    int tid0 = blockIdx.x*blockDim.x + threadIdx.x;
    int stride = gridDim.x*blockDim.x;
    for(int i = tid0; i < 2*K2*N4H; i += stride){
        int jj = i & (N4H-1);
        int r  = i >> 11;
        int k  = r & (K2-1);
        int dir = r >> 11;
        int j = ((jj&3)<<9) + (jj>>2);
        const float* Wih = dir ? Wb_ih : Wf_ih;
        const float* Whh = dir ? Wb_hh : Wf_hh;
        float vv = (k < 1536) ? Wih[j*1536 + k] : Whh[j*512 + (k-1536)];
        g_Wcat[i] = vv;
    }
    if(tid0 < 2*N4H){
        int jj = tid0 & (N4H-1); int dir = tid0 >> 11;
        int j = ((jj&3)<<9) + (jj>>2);
        g_bcat[tid0] = dir ? bb[j] : bf[j];
    }
    if(tid0 < HH*HH){
        int n = tid0 & (HH-1); int k = tid0 >> 9;
        g_WdecT[k*HH + n] = W_dec[n*HH + k];
    }
}

// ---------------- enc_proj GEMM -------------------------------------------------
__global__ void k_enc_gemm(const float* __restrict__ A, const float* __restrict__ Bm,
                           const float* __restrict__ bias){
    __shared__ float As[16][68];
    __shared__ float Bs[16][68];
    const int Kk = DD, Nn = HH;
    int n0 = blockIdx.x*64, m0 = blockIdx.y*64;
    int tid = threadIdx.x;
    int tm = tid>>4, tn = tid&15;
    float acc[4][4];
    #pragma unroll
    for(int i=0;i<4;i++)
        #pragma unroll
        for(int j=0;j<4;j++) acc[i][j] = bias[n0 + tn*4 + j];

    int lrow = tid>>2, lkq = (tid&3)*4;
    for(int k0=0;k0<Kk;k0+=16){
        float4 av = *(const float4*)&A[(long)(m0+lrow)*Kk + k0 + lkq];
        float4 bv = *(const float4*)&Bm[(long)(n0+lrow)*Kk + k0 + lkq];
        __syncthreads();
        As[lkq+0][lrow]=av.x; As[lkq+1][lrow]=av.y; As[lkq+2][lrow]=av.z; As[lkq+3][lrow]=av.w;
        Bs[lkq+0][lrow]=bv.x; Bs[lkq+1][lrow]=bv.y; Bs[lkq+2][lrow]=bv.z; Bs[lkq+3][lrow]=bv.w;
        __syncthreads();
        #pragma unroll
        for(int kk=0;kk<16;kk++){
            float4 a4 = *(const float4*)&As[kk][tm*4];
            float4 b4 = *(const float4*)&Bs[kk][tn*4];
            float aa[4] = {a4.x,a4.y,a4.z,a4.w};
            float bb4[4] = {b4.x,b4.y,b4.z,b4.w};
            #pragma unroll
            for(int i=0;i<4;i++)
                #pragma unroll
                for(int j=0;j<4;j++) acc[i][j] += aa[i]*bb4[j];
        }
    }
    #pragma unroll
    for(int i=0;i<4;i++)
        #pragma unroll
        for(int j=0;j<4;j++)
            g_enc[(long)(m0+tm*4+i)*Nn + n0 + tn*4 + j] = acc[i][j];
}

// ---------------- persistent recurrent kernel (1024 threads/block) --------------
union SH {
    struct { float d0[HH], d1[HH], vs[HH]; } a;                      // 6KB
    struct { float w0[TT], w1[TT]; float red0[16], red1[16]; } b;    // 4.1KB
    struct { float As[16][36]; float4 Bs[16][128]; } c;              // 34.3KB
    struct { float Hs[32][64]; float Ws[64][64]; } e;                // 24KB
};

__global__ void __launch_bounds__(1024, 1)
k_persist(const float* __restrict__ x, const float* __restrict__ v,
          const float* __restrict__ b_dec, int G){
    __shared__ SH sh;
    const int tid = threadIdx.x;
    const int lane = tid & 31, warp = tid >> 5;
    unsigned int bt = (unsigned)G;

    for(int s=0; s<TT; s++){
        // ======== Phase A: attention scores ========
        for(int task = blockIdx.x; task < 128; task += G){
            int b = task >> 2, tp = task & 3;
            if(tid < HH){
                float a0=0.f, a1=0.f;
                #pragma unroll
                for(int kc=0;kc<8;kc++){
                    a0 += g_decp[((kc*2+0)*BB + b)*HH + tid];
                    a1 += g_decp[((kc*2+1)*BB + b)*HH + tid];
                }
                sh.a.d0[tid]=a0; sh.a.d1[tid]=a1; sh.a.vs[tid]=v[tid];
            }
            __syncthreads();
            #pragma unroll 1
            for(int i=0;i<4;i++){
                int t = tp*128 + warp*4 + i;
                const float* e = &g_enc[(b*TT + t)*HH];
                float s0=0.f, s1=0.f;
                #pragma unroll
                for(int j=0;j<16;j++){
                    int h = lane + j*32;
                    float ev = e[h];
                    float vv = sh.a.vs[h];
                    s0 += vv*tanh_acc(ev + sh.a.d0[h]);
                    s1 += vv*tanh_acc(ev + sh.a.d1[h]);
                }
                s0 = warpSum(s0); s1 = warpSum(s1);
                if(lane==0){
                    g_scores[b*TT + t] = s0;
                    g_scores[(BB + b)*TT + t] = s1;
                }
            }
            __syncthreads();
        }
        gbar(bt); bt += G;

        // ======== Phase B: softmax + context partials (256 tasks: b x tp8) ======
        for(int task = blockIdx.x; task < 256; task += G){
            int b = task >> 3, tp = task & 7;
            int t0 = tp*64;
            if(tid < TT){
                sh.b.w0[tid] = g_scores[b*TT + tid];
                sh.b.w1[tid] = g_scores[(BB+b)*TT + tid];
            }
            __syncthreads();
            if(warp < 16){
                float m0 = warpMax(sh.b.w0[tid]);
                float m1 = warpMax(sh.b.w1[tid]);
                if(lane==0){ sh.b.red0[warp]=m0; sh.b.red1[warp]=m1; }
            }
            __syncthreads();
            float m0 = sh.b.red0[0], m1 = sh.b.red1[0];
            #pragma unroll
            for(int j=1;j<16;j++){ m0=fmaxf(m0,sh.b.red0[j]); m1=fmaxf(m1,sh.b.red1[j]); }
            __syncthreads();
            if(warp < 16){
                float e0 = __expf(sh.b.w0[tid]-m0); sh.b.w0[tid]=e0;
                float e1 = __expf(sh.b.w1[tid]-m1); sh.b.w1[tid]=e1;
                float z0 = warpSum(e0), z1 = warpSum(e1);
                if(lane==0){ sh.b.red0[warp]=z0; sh.b.red1[warp]=z1; }
            }
            __syncthreads();
            float z0=0.f, z1=0.f;
            #pragma unroll
            for(int j=0;j<16;j++){ z0+=sh.b.red0[j]; z1+=sh.b.red1[j]; }
            float inv0 = __fdividef(1.0f, z0), inv1 = __fdividef(1.0f, z1);

            if(tid < DD){
                float a0=0.f, a1=0.f;
                #pragma unroll 4
                for(int t=0;t<64;t++){
                    float ww0 = sh.b.w0[t0+t]*inv0;
                    float ww1 = sh.b.w1[t0+t]*inv1;
                    float xv = x[(long)(b*TT + t0 + t)*DD + tid];
                    a0 += ww0*xv; a1 += ww1*xv;
                }
                g_ctxp[((tp*2+0)*BB + b)*DD + tid] = a0;
                g_ctxp[((tp*2+1)*BB + b)*DD + tid] = a1;
            }
            __syncthreads();
        }
        gbar(bt); bt += G;

        // ======== Phase C: gates GEMM partials (M32 x N512 x K128 per task) ====
        for(int task = blockIdx.x; task < 128; task += G){
            int dir = task & 1, nt = (task>>1)&3, kc = task>>3;
            int n0 = nt*512, k0 = kc*128;
            int t = dir ? (TT-1-s) : s;
            int bg = tid>>7, nc = tid&127;
            float acc[4][4];
            #pragma unroll
            for(int i=0;i<4;i++)
                #pragma unroll
                for(int j=0;j<4;j++) acc[i][j]=0.f;

            for(int kb=0;kb<128;kb+=16){
                __syncthreads();
                if(tid < 512){
                    int kk = tid&15, bi = tid>>4;
                    int k = k0 + kb + kk;
                    float val;
                    if(k0 < 768){
                        val = 0.f;
                        #pragma unroll
                        for(int p=0;p<8;p++)
                            val += g_ctxp[((p*2+dir)*BB+bi)*DD + k];
                    } else if(k0 < 1536){
                        val = x[(long)(bi*TT + t)*DD + (k-768)];
                    } else {
                        val = g_h[(dir*BB+bi)*HH + (k-1536)];
                    }
                    sh.c.As[kk][bi] = val;
                }
                const float4* wsrc = (const float4*)&g_Wcat[dir*(K2*N4H) + (k0+kb)*N4H + n0];
                #pragma unroll
                for(int r=0;r<2;r++){
                    int idx = tid + 1024*r;
                    int kk = idx>>7, c4 = idx&127;
                    sh.c.Bs[kk][c4] = wsrc[kk*512 + c4];
                }
                __syncthreads();
                #pragma unroll
                for(int kk=0;kk<16;kk++){
                    float4 b4 = sh.c.Bs[kk][nc];
                    float4 a4 = *(const float4*)&sh.c.As[kk][bg*4];
                    float av[4] = {a4.x,a4.y,a4.z,a4.w};
                    float bv[4] = {b4.x,b4.y,b4.z,b4.w};
                    #pragma unroll
                    for(int i=0;i<4;i++)
                        #pragma unroll
                        for(int j=0;j<4;j++) acc[i][j] += av[i]*bv[j];
                }
            }
            #pragma unroll
            for(int i=0;i<4;i++){
                int bi = bg*4 + i;
                *(float4*)&g_gpart[((long)(kc*2+dir)*BB + bi)*N4H + n0 + nc*4] =
                    make_float4(acc[i][0],acc[i][1],acc[i][2],acc[i][3]);
            }
            __syncthreads();
        }
        gbar(bt); bt += G;

        // ======== Phase D: LSTM pointwise ========
        {
            int idx = blockIdx.x*1024 + tid;
            if(idx < 2*BB*HH){
                int hc = idx & (HH-1);
                int b  = (idx>>9) & (BB-1);
                int dir = idx>>14;
                int t = dir ? (TT-1-s) : s;
                float4 gs = make_float4(0.f,0.f,0.f,0.f);
                #pragma unroll
                for(int p=0;p<16;p++){
                    float4 gp = *(const float4*)&g_gpart[((long)(p*2+dir)*BB + b)*N4H + hc*4];
                    gs.x+=gp.x; gs.y+=gp.y; gs.z+=gp.z; gs.w+=gp.w;
                }
                float4 bc = *(const float4*)&g_bcat[dir*N4H + hc*4];
                float ig = sigm(gs.x+bc.x);
                float fg = sigm(gs.y+bc.y);
                float gg = tanh_acc(gs.z+bc.z);
                float og = sigm(gs.w+bc.w);
                int ix = (dir*BB+b)*HH + hc;
                float c = fg*g_c[ix] + ig*gg;
                float h = og*tanh_acc(c);
                g_c[ix]=c; g_h[ix]=h;
                g_hs[((dir*TT+t)*BB + b)*HH + hc] = h;
            }
        }
        gbar(bt); bt += G;

        // ======== Phase E: dec partials (h @ WdecT), K-split ========
        for(int task = blockIdx.x; task < 128; task += G){
            int dir = task & 1, nt = (task>>1)&7, kc = task>>4;
            int n0 = nt*64, k0 = kc*64;
            #pragma unroll
            for(int r=0;r<2;r++){
                int lin = tid + 1024*r;
                int bi = lin>>6, k = lin&63;
                sh.e.Hs[bi][k] = g_h[(dir*BB+bi)*HH + k0 + k];
            }
            #pragma unroll
            for(int r=0;r<4;r++){
                int lin = tid + 1024*r;
                int k = lin>>6, n = lin&63;
                sh.e.Ws[k][n] = g_WdecT[(k0+k)*HH + n0 + n];
            }
            __syncthreads();
            int tb = tid>>5, tn = tid&31;
            float acc0=0.f, acc1=0.f;
            #pragma unroll 8
            for(int k=0;k<64;k++){
                float a = sh.e.Hs[tb][k];
                float2 w2 = *(const float2*)&sh.e.Ws[k][tn*2];
                acc0 += a*w2.x; acc1 += a*w2.y;
            }
            int n = n0 + tn*2;
            float bias0 = (kc==0) ? b_dec[n]   : 0.f;
            float bias1 = (kc==0) ? b_dec[n+1] : 0.f;
            g_decp[((kc*2+dir)*BB + tb)*HH + n]   = acc0 + bias0;
            g_decp[((kc*2+dir)*BB + tb)*HH + n+1] = acc1 + bias1;
            __syncthreads();
        }
        gbar(bt); bt += G;
    }
}

// ---------------- final head ----------------------------------------------------
__global__ void k_head(const float* __restrict__ W_head, const float* __restrict__ b_head,
                       float* __restrict__ out){
    __shared__ float Ws[CC*2*HH];   // 28KB
    int tid = threadIdx.x;
    for(int i=tid;i<CC*2*HH;i+=256) Ws[i] = W_head[i];
    __syncthreads();
    int warp = tid>>5, lane = tid&31;
    int m = blockIdx.x*8 + warp;
    int b = m >> 9, t = m & (TT-1);
    const float* hf = &g_hs[((0*TT+t)*BB + b)*HH];
    const float* hb = &g_hs[((1*TT+t)*BB + b)*HH];
    float acc[CC];
    #pragma unroll
    for(int c=0;c<CC;c++) acc[c]=0.f;
    #pragma unroll 4
    for(int i=0;i<16;i++){
        int k = lane + i*32;
        float vf = hf[k];
        float vb = hb[k];
        #pragma unroll
        for(int c=0;c<CC;c++){
            acc[c] += vf*Ws[c*1024 + k] + vb*Ws[c*1024 + 512 + k];
        }
    }
    float res = 0.f;
    #pragma unroll
    for(int c=0;c<CC;c++){
        float r = warpSum(acc[c]);
        if(lane==c) res = r;
    }
    if(lane < CC) out[m*CC + lane] = res + b_head[lane];
}

// ---------------- launch ----------------
extern "C" void kernel_launch(void* const* d_in, const int* in_sizes, int n_in,
                              void* d_out, int out_size){
    const float* x      = (const float*)d_in[0];
    const float* Wf_ih  = (const float*)d_in[1];
    const float* Wf_hh  = (const float*)d_in[2];
    const float* bf     = (const float*)d_in[3];
    const float* Wb_ih  = (const float*)d_in[4];
    const float* Wb_hh  = (const float*)d_in[5];
    const float* bb     = (const float*)d_in[6];
    const float* W_enc  = (const float*)d_in[7];
    const float* b_enc  = (const float*)d_in[8];
    const float* W_dec  = (const float*)d_in[9];
    const float* b_dec  = (const float*)d_in[10];
    const float* v      = (const float*)d_in[11];
    const float* W_head = (const float*)d_in[12];
    const float* b_head = (const float*)d_in[13];
    float* out = (float*)d_out;

    int dev = 0;
    cudaGetDevice(&dev);
    int nsm = 128;
    cudaDeviceGetAttribute(&nsm, cudaDevAttrMultiProcessorCount, dev);
    int G = nsm;

    k_init<<<1024, 256>>>(b_dec);
    k_prep<<<2048, 256>>>(Wf_ih, Wf_hh, bf, Wb_ih, Wb_hh, bb, W_dec);
    k_enc_gemm<<<dim3(8, 256), 256>>>(x, W_enc, b_enc);
    k_persist<<<G, 1024>>>(x, v, b_dec, G);
    k_head<<<2048, 256>>>(W_head, b_head, out);
}

// round 7
// speedup vs baseline: 1.4136x; 1.2730x over previous
#include <cuda_runtime.h>
#include <cuda_bf16.h>

#define BB 32
#define TT 512
#define DD 768
#define HH 512
#define CC 7
#define K2 2048          // gates GEMM K = ctx(768) + xt(768) + h(512)
#define N4H 2048         // 4*H

// ---------------- device state (static scratch; no allocations) ----------------
__device__ float g_enc[BB*TT*HH];          // [b][t][h]  enc_proj
__device__ float g_Wcat[2*K2*N4H];         // [dir][k][jj] transposed/interleaved weights
__device__ float g_bcat[2*N4H];            // [dir][jj]
__device__ float g_WdecT[HH*HH];           // [k][n]
__device__ float g_h[2*BB*HH];
__device__ float g_c[2*BB*HH];
__device__ float g_decp[8*2*BB*HH];        // [kc8][dir][b][n] dec partials
__device__ float g_scores[2*BB*TT];        // [dir][b][t]
__device__ float g_ctxp[4*2*BB*DD];        // [part4][dir][b][d]
__device__ float g_gpart[8*2*BB*N4H];      // [kc8][dir][b][jj]  (4MB, L2-resident)
__device__ float g_hs[2*TT*BB*HH];         // [dir][t][b][h]
__device__ unsigned int g_arrive;

// ---------------- helpers ----------------
__device__ __forceinline__ float fast_tanh(float x){
    float y; asm("tanh.approx.f32 %0, %1;" : "=f"(y) : "f"(x)); return y;
}
__device__ __forceinline__ float tanh_acc(float x){
    float e = __expf(x + x);
    return 1.0f - __fdividef(2.0f, e + 1.0f);
}
__device__ __forceinline__ float sigm(float x){ return 1.0f/(1.0f+__expf(-x)); }
__device__ __forceinline__ float warpMax(float v){
    #pragma unroll
    for(int o=16;o;o>>=1) v = fmaxf(v, __shfl_xor_sync(0xffffffffu, v, o));
    return v;
}
__device__ __forceinline__ float warpSum(float v){
    #pragma unroll
    for(int o=16;o;o>>=1) v += __shfl_xor_sync(0xffffffffu, v, o);
    return v;
}

// ---------------- grid barrier (monotonic counter, reset by k_init) ------------
__device__ __forceinline__ void gbar(unsigned int target){
    __syncthreads();
    if(threadIdx.x == 0){
        __threadfence();
        atomicAdd(&g_arrive, 1u);
        unsigned int vv;
        unsigned int ns = 32;
        #pragma unroll 1
        do {
            asm volatile("ld.acquire.gpu.u32 %0, [%1];" : "=r"(vv) : "l"(&g_arrive));
            if(vv >= target) break;
            __nanosleep(ns);
            if(ns < 256) ns <<= 1;
        } while(true);
    }
    __syncthreads();
}

// ---------------- init ----------------------------------------------------------
__global__ void k_init(const float* __restrict__ b_dec){
    int i = blockIdx.x*blockDim.x + threadIdx.x;       // grid covers 262144
    if(i == 0) g_arrive = 0u;
    if(i < 2*BB*HH){ g_h[i]=0.f; g_c[i]=0.f; }
    if(i < 8*2*BB*HH){
        int kc = i >> 15;
        g_decp[i] = (kc==0) ? b_dec[i & (HH-1)] : 0.f;
    }
}

// ---------------- weight prep ---------------------------------------------------
__global__ void k_prep(const float* __restrict__ Wf_ih, const float* __restrict__ Wf_hh,
                       const float* __restrict__ bf,
                       const float* __restrict__ Wb_ih, const float* __restrict__ Wb_hh,
                       const float* __restrict__ bb,
                       const float* __restrict__ W_dec){
    int tid0 = blockIdx.x*blockDim.x + threadIdx.x;
    int stride = gridDim.x*blockDim.x;
    for(int i = tid0; i < 2*K2*N4H; i += stride){
        int jj = i & (N4H-1);
        int r  = i >> 11;
        int k  = r & (K2-1);
        int dir = r >> 11;
        int j = ((jj&3)<<9) + (jj>>2);
        const float* Wih = dir ? Wb_ih : Wf_ih;
        const float* Whh = dir ? Wb_hh : Wf_hh;
        float vv = (k < 1536) ? Wih[j*1536 + k] : Whh[j*512 + (k-1536)];
        g_Wcat[i] = vv;
    }
    if(tid0 < 2*N4H){
        int jj = tid0 & (N4H-1); int dir = tid0 >> 11;
        int j = ((jj&3)<<9) + (jj>>2);
        g_bcat[tid0] = dir ? bb[j] : bf[j];
    }
    if(tid0 < HH*HH){
        int n = tid0 & (HH-1); int k = tid0 >> 9;
        g_WdecT[k*HH + n] = W_dec[n*HH + k];
    }
}

// ---------------- enc_proj GEMM -------------------------------------------------
__global__ void k_enc_gemm(const float* __restrict__ A, const float* __restrict__ Bm,
                           const float* __restrict__ bias){
    __shared__ float As[16][68];
    __shared__ float Bs[16][68];
    const int Kk = DD, Nn = HH;
    int n0 = blockIdx.x*64, m0 = blockIdx.y*64;
    int tid = threadIdx.x;
    int tm = tid>>4, tn = tid&15;
    float acc[4][4];
    #pragma unroll
    for(int i=0;i<4;i++)
        #pragma unroll
        for(int j=0;j<4;j++) acc[i][j] = bias[n0 + tn*4 + j];

    int lrow = tid>>2, lkq = (tid&3)*4;
    for(int k0=0;k0<Kk;k0+=16){
        float4 av = *(const float4*)&A[(long)(m0+lrow)*Kk + k0 + lkq];
        float4 bv = *(const float4*)&Bm[(long)(n0+lrow)*Kk + k0 + lkq];
        __syncthreads();
        As[lkq+0][lrow]=av.x; As[lkq+1][lrow]=av.y; As[lkq+2][lrow]=av.z; As[lkq+3][lrow]=av.w;
        Bs[lkq+0][lrow]=bv.x; Bs[lkq+1][lrow]=bv.y; Bs[lkq+2][lrow]=bv.z; Bs[lkq+3][lrow]=bv.w;
        __syncthreads();
        #pragma unroll
        for(int kk=0;kk<16;kk++){
            float4 a4 = *(const float4*)&As[kk][tm*4];
            float4 b4 = *(const float4*)&Bs[kk][tn*4];
            float aa[4] = {a4.x,a4.y,a4.z,a4.w};
            float bb4[4] = {b4.x,b4.y,b4.z,b4.w};
            #pragma unroll
            for(int i=0;i<4;i++)
                #pragma unroll
                for(int j=0;j<4;j++) acc[i][j] += aa[i]*bb4[j];
        }
    }
    #pragma unroll
    for(int i=0;i<4;i++)
        #pragma unroll
        for(int j=0;j<4;j++)
            g_enc[(long)(m0+tm*4+i)*Nn + n0 + tn*4 + j] = acc[i][j];
}

// ---------------- persistent recurrent kernel (1024 threads/block) --------------
union SH {
    struct { float d0[HH], d1[HH], vs[HH]; } a;                      // 6KB
    struct { float w0[TT], w1[TT]; float red0[16], red1[16]; } b;    // 4.1KB
    struct { float As[16][36]; float4 Bs[16][64]; } c;               // 18.6KB
    struct { float Hs[32][64]; float Ws[64][64]; } e;                // 24KB
};

__global__ void __launch_bounds__(1024, 1)
k_persist(const float* __restrict__ x, const float* __restrict__ v,
          const float* __restrict__ b_dec, int G){
    __shared__ SH sh;
    const int tid = threadIdx.x;
    const int lane = tid & 31, warp = tid >> 5;
    unsigned int bt = (unsigned)G;

    for(int s=0; s<TT; s++){
        // ======== Phase A: attention scores (128 tasks: b x tp4) ========
        for(int task = blockIdx.x; task < 128; task += G){
            int b = task >> 2, tp = task & 3;
            if(tid < HH){
                float a0=0.f, a1=0.f;
                #pragma unroll
                for(int kc=0;kc<8;kc++){
                    a0 += g_decp[((kc*2+0)*BB + b)*HH + tid];
                    a1 += g_decp[((kc*2+1)*BB + b)*HH + tid];
                }
                sh.a.d0[tid]=a0; sh.a.d1[tid]=a1; sh.a.vs[tid]=v[tid];
            }
            __syncthreads();
            #pragma unroll 1
            for(int i=0;i<4;i++){
                int t = tp*128 + warp*4 + i;
                const float* e = &g_enc[(b*TT + t)*HH];
                float s0=0.f, s1=0.f;
                #pragma unroll
                for(int j=0;j<16;j++){
                    int h = lane + j*32;
                    float ev = e[h];
                    float vv = sh.a.vs[h];
                    s0 += vv*fast_tanh(ev + sh.a.d0[h]);
                    s1 += vv*fast_tanh(ev + sh.a.d1[h]);
                }
                s0 = warpSum(s0); s1 = warpSum(s1);
                if(lane==0){
                    g_scores[b*TT + t] = s0;
                    g_scores[(BB + b)*TT + t] = s1;
                }
            }
            __syncthreads();
        }
        gbar(bt); bt += G;

        // ======== Phase B: softmax + context partials (128 tasks: b x tp4) ======
        for(int task = blockIdx.x; task < 128; task += G){
            int b = task >> 2, tp = task & 3;
            int t0 = tp*128;
            if(tid < TT){
                sh.b.w0[tid] = g_scores[b*TT + tid];
                sh.b.w1[tid] = g_scores[(BB+b)*TT + tid];
            }
            __syncthreads();
            if(warp < 16){
                float m0 = warpMax(sh.b.w0[tid]);
                float m1 = warpMax(sh.b.w1[tid]);
                if(lane==0){ sh.b.red0[warp]=m0; sh.b.red1[warp]=m1; }
            }
            __syncthreads();
            float m0 = sh.b.red0[0], m1 = sh.b.red1[0];
            #pragma unroll
            for(int j=1;j<16;j++){ m0=fmaxf(m0,sh.b.red0[j]); m1=fmaxf(m1,sh.b.red1[j]); }
            __syncthreads();
            if(warp < 16){
                float e0 = __expf(sh.b.w0[tid]-m0); sh.b.w0[tid]=e0;
                float e1 = __expf(sh.b.w1[tid]-m1); sh.b.w1[tid]=e1;
                float z0 = warpSum(e0), z1 = warpSum(e1);
                if(lane==0){ sh.b.red0[warp]=z0; sh.b.red1[warp]=z1; }
            }
            __syncthreads();
            float z0=0.f, z1=0.f;
            #pragma unroll
            for(int j=0;j<16;j++){ z0+=sh.b.red0[j]; z1+=sh.b.red1[j]; }
            float inv0 = __fdividef(1.0f, z0), inv1 = __fdividef(1.0f, z1);

            if(tid < DD){
                float a0=0.f, a1=0.f;
                #pragma unroll 8
                for(int t=0;t<128;t++){
                    float ww0 = sh.b.w0[t0+t]*inv0;
                    float ww1 = sh.b.w1[t0+t]*inv1;
                    float xv = x[(long)(b*TT + t0 + t)*DD + tid];
                    a0 += ww0*xv; a1 += ww1*xv;
                }
                g_ctxp[((tp*2+0)*BB + b)*DD + tid] = a0;
                g_ctxp[((tp*2+1)*BB + b)*DD + tid] = a1;
            }
            __syncthreads();
        }
        gbar(bt); bt += G;

        // ======== Phase C: gates GEMM partials (128 tasks: dir x nt8(256) x kc8(256))
        for(int task = blockIdx.x; task < 128; task += G){
            int dir = task & 1, nt = (task>>1)&7, kc = task>>4;
            int n0 = nt*256, k0 = kc*256;
            int t = dir ? (TT-1-s) : s;
            int bg = tid>>7, nc = tid&127;       // 8 b-groups x 128 n-pairs
            float acc[4][2];
            #pragma unroll
            for(int i=0;i<4;i++){ acc[i][0]=0.f; acc[i][1]=0.f; }

            for(int kb=0;kb<256;kb+=16){
                __syncthreads();
                if(tid < 512){
                    int kk = tid&15, bi = tid>>4;
                    int k = k0 + kb + kk;
                    float val;
                    if(k0 < 768){
                        val = g_ctxp[((0*2+dir)*BB+bi)*DD + k]
                            + g_ctxp[((1*2+dir)*BB+bi)*DD + k]
                            + g_ctxp[((2*2+dir)*BB+bi)*DD + k]
                            + g_ctxp[((3*2+dir)*BB+bi)*DD + k];
                    } else if(k0 < 1536){
                        val = x[(long)(bi*TT + t)*DD + (k-768)];
                    } else {
                        val = g_h[(dir*BB+bi)*HH + (k-1536)];
                    }
                    sh.c.As[kk][bi] = val;
                }
                // B tile 16k x 256n : 1024 float4 loads, 1 per thread
                {
                    int kk = tid>>6, c4 = tid&63;
                    sh.c.Bs[kk][c4] = *(const float4*)&g_Wcat[dir*(K2*N4H) + (k0+kb+kk)*N4H + n0 + c4*4];
                }
                __syncthreads();
                #pragma unroll
                for(int kk=0;kk<16;kk++){
                    float2 b2 = *(((const float2*)sh.c.Bs[kk]) + nc);
                    float4 a4 = *(const float4*)&sh.c.As[kk][bg*4];
                    acc[0][0]+=a4.x*b2.x; acc[0][1]+=a4.x*b2.y;
                    acc[1][0]+=a4.y*b2.x; acc[1][1]+=a4.y*b2.y;
                    acc[2][0]+=a4.z*b2.x; acc[2][1]+=a4.z*b2.y;
                    acc[3][0]+=a4.w*b2.x; acc[3][1]+=a4.w*b2.y;
                }
            }
            #pragma unroll
            for(int i=0;i<4;i++){
                int bi = bg*4 + i;
                *(float2*)&g_gpart[((long)(kc*2+dir)*BB + bi)*N4H + n0 + nc*2] =
                    make_float2(acc[i][0], acc[i][1]);
            }
            __syncthreads();
        }
        gbar(bt); bt += G;

        // ======== Phase D: LSTM pointwise (grid-strided) ========
        for(int idx = blockIdx.x*1024 + tid; idx < 2*BB*HH; idx += G*1024){
            int hc = idx & (HH-1);
            int b  = (idx>>9) & (BB-1);
            int dir = idx>>14;
            int t = dir ? (TT-1-s) : s;
            float4 gs = make_float4(0.f,0.f,0.f,0.f);
            #pragma unroll
            for(int p=0;p<8;p++){
                float4 gp = *(const float4*)&g_gpart[((long)(p*2+dir)*BB + b)*N4H + hc*4];
                gs.x+=gp.x; gs.y+=gp.y; gs.z+=gp.z; gs.w+=gp.w;
            }
            float4 bc = *(const float4*)&g_bcat[dir*N4H + hc*4];
            float ig = sigm(gs.x+bc.x);
            float fg = sigm(gs.y+bc.y);
            float gg = tanh_acc(gs.z+bc.z);
            float og = sigm(gs.w+bc.w);
            int ix = (dir*BB+b)*HH + hc;
            float c = fg*g_c[ix] + ig*gg;
            float h = og*tanh_acc(c);
            g_c[ix]=c; g_h[ix]=h;
            g_hs[((dir*TT+t)*BB + b)*HH + hc] = h;
        }
        gbar(bt); bt += G;

        // ======== Phase E: dec partials (h @ WdecT), 128 tasks: dir x nt8(64) x kc8(64)
        for(int task = blockIdx.x; task < 128; task += G){
            int dir = task & 1, nt = (task>>1)&7, kc = task>>4;
            int n0 = nt*64, k0 = kc*64;
            #pragma unroll
            for(int r=0;r<2;r++){
                int lin = tid + 1024*r;
                int bi = lin>>6, k = lin&63;
                sh.e.Hs[bi][k] = g_h[(dir*BB+bi)*HH + k0 + k];
            }
            #pragma unroll
            for(int r=0;r<4;r++){
                int lin = tid + 1024*r;
                int k = lin>>6, n = lin&63;
                sh.e.Ws[k][n] = g_WdecT[(k0+k)*HH + n0 + n];
            }
            __syncthreads();
            int tb = tid>>5, tn = tid&31;
            float acc0=0.f, acc1=0.f;
            #pragma unroll 8
            for(int k=0;k<64;k++){
                float a = sh.e.Hs[tb][k];
                float2 w2 = *(const float2*)&sh.e.Ws[k][tn*2];
                acc0 += a*w2.x; acc1 += a*w2.y;
            }
            int n = n0 + tn*2;
            float bias0 = (kc==0) ? b_dec[n]   : 0.f;
            float bias1 = (kc==0) ? b_dec[n+1] : 0.f;
            g_decp[((kc*2+dir)*BB + tb)*HH + n]   = acc0 + bias0;
            g_decp[((kc*2+dir)*BB + tb)*HH + n+1] = acc1 + bias1;
            __syncthreads();
        }
        gbar(bt); bt += G;
    }
}

// ---------------- final head ----------------------------------------------------
__global__ void k_head(const float* __restrict__ W_head, const float* __restrict__ b_head,
                       float* __restrict__ out){
    __shared__ float Ws[CC*2*HH];   // 28KB
    int tid = threadIdx.x;
    for(int i=tid;i<CC*2*HH;i+=256) Ws[i] = W_head[i];
    __syncthreads();
    int warp = tid>>5, lane = tid&31;
    int m = blockIdx.x*8 + warp;
    int b = m >> 9, t = m & (TT-1);
    const float* hf = &g_hs[((0*TT+t)*BB + b)*HH];
    const float* hb = &g_hs[((1*TT+t)*BB + b)*HH];
    float acc[CC];
    #pragma unroll
    for(int c=0;c<CC;c++) acc[c]=0.f;
    #pragma unroll 4
    for(int i=0;i<16;i++){
        int k = lane + i*32;
        float vf = hf[k];
        float vb = hb[k];
        #pragma unroll
        for(int c=0;c<CC;c++){
            acc[c] += vf*Ws[c*1024 + k] + vb*Ws[c*1024 + 512 + k];
        }
    }
    float res = 0.f;
    #pragma unroll
    for(int c=0;c<CC;c++){
        float r = warpSum(acc[c]);
        if(lane==c) res = r;
    }
    if(lane < CC) out[m*CC + lane] = res + b_head[lane];
}

// ---------------- launch ----------------
extern "C" void kernel_launch(void* const* d_in, const int* in_sizes, int n_in,
                              void* d_out, int out_size){
    const float* x      = (const float*)d_in[0];
    const float* Wf_ih  = (const float*)d_in[1];
    const float* Wf_hh  = (const float*)d_in[2];
    const float* bf     = (const float*)d_in[3];
    const float* Wb_ih  = (const float*)d_in[4];
    const float* Wb_hh  = (const float*)d_in[5];
    const float* bb     = (const float*)d_in[6];
    const float* W_enc  = (const float*)d_in[7];
    const float* b_enc  = (const float*)d_in[8];
    const float* W_dec  = (const float*)d_in[9];
    const float* b_dec  = (const float*)d_in[10];
    const float* v      = (const float*)d_in[11];
    const float* W_head = (const float*)d_in[12];
    const float* b_head = (const float*)d_in[13];
    float* out = (float*)d_out;

    int dev = 0;
    cudaGetDevice(&dev);
    int nsm = 128;
    cudaDeviceGetAttribute(&nsm, cudaDevAttrMultiProcessorCount, dev);
    int G = nsm;

    k_init<<<1024, 256>>>(b_dec);
    k_prep<<<2048, 256>>>(Wf_ih, Wf_hh, bf, Wb_ih, Wb_hh, bb, W_dec);
    k_enc_gemm<<<dim3(8, 256), 256>>>(x, W_enc, b_enc);
    k_persist<<<G, 1024>>>(x, v, b_dec, G);
    k_head<<<2048, 256>>>(W_head, b_head, out);
}

// round 8
// speedup vs baseline: 1.6172x; 1.1440x over previous
#include <cuda_runtime.h>
#include <cuda_bf16.h>
#include <cstdint>

#define BB 32
#define TT 512
#define DD 768
#define HH 512
#define CC 7
#define K2 2048          // gates GEMM K = ctx(768) + xt(768) + h(512)
#define N4H 2048         // 4*H

// ---------------- device state (static scratch; no allocations) ----------------
__device__ float g_enc[BB*TT*HH];          // [b][t][h]  enc_proj
__device__ float g_WcatP[2*256*256*64];    // frag-packed tf32 weights [dir][k8][n8][lane][2]
__device__ float g_bcat[2*N4H];            // [dir][jj]
__device__ float g_WdecT[HH*HH];           // [k][n]
__device__ float g_h[2*BB*HH];
__device__ float g_c[2*BB*HH];
__device__ float g_decp[8*2*BB*HH];        // [kc8][dir][b][n] dec partials
__device__ float g_scores[2*BB*TT];        // [dir][b][t]
__device__ float g_ctxp[4*2*BB*DD];        // [part4][dir][b][d]
__device__ float g_gpart[8*2*BB*N4H];      // [kc8][dir][b][jj]  (4MB, L2-resident)
__device__ float g_hs[2*TT*BB*HH];         // [dir][t][b][h]
__device__ unsigned int g_arrive;

// ---------------- helpers ----------------
__device__ __forceinline__ float fast_tanh(float x){
    float y; asm("tanh.approx.f32 %0, %1;" : "=f"(y) : "f"(x)); return y;
}
__device__ __forceinline__ float tanh_acc(float x){
    float e = __expf(x + x);
    return 1.0f - __fdividef(2.0f, e + 1.0f);
}
__device__ __forceinline__ float sigm(float x){ return 1.0f/(1.0f+__expf(-x)); }
__device__ __forceinline__ float warpMax(float v){
    #pragma unroll
    for(int o=16;o;o>>=1) v = fmaxf(v, __shfl_xor_sync(0xffffffffu, v, o));
    return v;
}
__device__ __forceinline__ float warpSum(float v){
    #pragma unroll
    for(int o=16;o;o>>=1) v += __shfl_xor_sync(0xffffffffu, v, o);
    return v;
}
__device__ __forceinline__ uint32_t to_tf32(float f){
    uint32_t u; asm("cvt.rna.tf32.f32 %0, %1;" : "=r"(u) : "f"(f)); return u;
}
__device__ __forceinline__ void mma_tf32(float* c, const uint32_t* a, uint32_t b0, uint32_t b1){
    asm volatile("mma.sync.aligned.m16n8k8.row.col.f32.tf32.tf32.f32 "
                 "{%0,%1,%2,%3}, {%4,%5,%6,%7}, {%8,%9}, {%0,%1,%2,%3};"
                 : "+f"(c[0]), "+f"(c[1]), "+f"(c[2]), "+f"(c[3])
                 : "r"(a[0]), "r"(a[1]), "r"(a[2]), "r"(a[3]), "r"(b0), "r"(b1));
}

// ---------------- grid barrier (monotonic counter, reset by k_init) ------------
__device__ __forceinline__ void gbar(unsigned int target){
    __syncthreads();
    if(threadIdx.x == 0){
        asm volatile("red.release.gpu.global.add.u32 [%0], %1;"
                     :: "l"(&g_arrive), "r"(1u) : "memory");
        unsigned int vv;
        #pragma unroll 1
        do {
            asm volatile("ld.acquire.gpu.u32 %0, [%1];" : "=r"(vv) : "l"(&g_arrive));
            if(vv >= target) break;
            __nanosleep(64);
        } while(true);
    }
    __syncthreads();
}

// ---------------- init ----------------------------------------------------------
__global__ void k_init(const float* __restrict__ b_dec){
    int i = blockIdx.x*blockDim.x + threadIdx.x;       // grid covers 262144
    if(i == 0) g_arrive = 0u;
    if(i < 2*BB*HH){ g_h[i]=0.f; g_c[i]=0.f; }
    if(i < 8*2*BB*HH){
        int kc = i >> 15;
        g_decp[i] = (kc==0) ? b_dec[i & (HH-1)] : 0.f;
    }
}

// ---------------- weight prep: frag-packed tf32 Wcat, bcat, WdecT ---------------
__global__ void k_prep(const float* __restrict__ Wf_ih, const float* __restrict__ Wf_hh,
                       const float* __restrict__ bf,
                       const float* __restrict__ Wb_ih, const float* __restrict__ Wb_hh,
                       const float* __restrict__ bb,
                       const float* __restrict__ W_dec){
    int tid0 = blockIdx.x*blockDim.x + threadIdx.x;
    int stride = gridDim.x*blockDim.x;
    // packed items: [dir][k8 256][n8 256][lane 32] -> float2
    for(int i = tid0; i < 2*256*256*32; i += stride){
        int lane = i & 31;
        int n8 = (i>>5) & 255;
        int k8 = (i>>13) & 255;
        int dir = (i>>21) & 1;
        int gid = lane>>2, tg = lane&3;
        int n = n8*8 + gid;                       // jj (interleaved gate index)
        int j = ((n&3)<<9) + (n>>2);              // torch row: gate*512 + hcol
        int ka = k8*8 + tg;
        int kb = ka + 4;
        const float* Wih = dir ? Wb_ih : Wf_ih;
        const float* Whh = dir ? Wb_hh : Wf_hh;
        float wa = (ka < 1536) ? Wih[j*1536 + ka] : Whh[j*512 + (ka-1536)];
        float wb = (kb < 1536) ? Wih[j*1536 + kb] : Whh[j*512 + (kb-1536)];
        uint32_t ua = to_tf32(wa), ub = to_tf32(wb);
        float2* dst = (float2*)&g_WcatP[(size_t)i*2];
        *dst = make_float2(__uint_as_float(ua), __uint_as_float(ub));
    }
    if(tid0 < 2*N4H){
        int jj = tid0 & (N4H-1); int dir = tid0 >> 11;
        int j = ((jj&3)<<9) + (jj>>2);
        g_bcat[tid0] = dir ? bb[j] : bf[j];
    }
    if(tid0 < HH*HH){
        int n = tid0 & (HH-1); int k = tid0 >> 9;
        g_WdecT[k*HH + n] = W_dec[n*HH + k];
    }
}

// ---------------- enc_proj GEMM -------------------------------------------------
__global__ void k_enc_gemm(const float* __restrict__ A, const float* __restrict__ Bm,
                           const float* __restrict__ bias){
    __shared__ float As[16][68];
    __shared__ float Bs[16][68];
    const int Kk = DD, Nn = HH;
    int n0 = blockIdx.x*64, m0 = blockIdx.y*64;
    int tid = threadIdx.x;
    int tm = tid>>4, tn = tid&15;
    float acc[4][4];
    #pragma unroll
    for(int i=0;i<4;i++)
        #pragma unroll
        for(int j=0;j<4;j++) acc[i][j] = bias[n0 + tn*4 + j];

    int lrow = tid>>2, lkq = (tid&3)*4;
    for(int k0=0;k0<Kk;k0+=16){
        float4 av = *(const float4*)&A[(long)(m0+lrow)*Kk + k0 + lkq];
        float4 bv = *(const float4*)&Bm[(long)(n0+lrow)*Kk + k0 + lkq];
        __syncthreads();
        As[lkq+0][lrow]=av.x; As[lkq+1][lrow]=av.y; As[lkq+2][lrow]=av.z; As[lkq+3][lrow]=av.w;
        Bs[lkq+0][lrow]=bv.x; Bs[lkq+1][lrow]=bv.y; Bs[lkq+2][lrow]=bv.z; Bs[lkq+3][lrow]=bv.w;
        __syncthreads();
        #pragma unroll
        for(int kk=0;kk<16;kk++){
            float4 a4 = *(const float4*)&As[kk][tm*4];
            float4 b4 = *(const float4*)&Bs[kk][tn*4];
            float aa[4] = {a4.x,a4.y,a4.z,a4.w};
            float bb4[4] = {b4.x,b4.y,b4.z,b4.w};
            #pragma unroll
            for(int i=0;i<4;i++)
                #pragma unroll
                for(int j=0;j<4;j++) acc[i][j] += aa[i]*bb4[j];
        }
    }
    #pragma unroll
    for(int i=0;i<4;i++)
        #pragma unroll
        for(int j=0;j<4;j++)
            g_enc[(long)(m0+tm*4+i)*Nn + n0 + tn*4 + j] = acc[i][j];
}

// ---------------- persistent recurrent kernel (1024 threads/block) --------------
union SH {
    struct { float d0[HH], d1[HH], vs[HH]; } a;                      // 6KB
    struct { float w0[TT], w1[TT]; float red0[16], red1[16]; } b;    // 4.1KB
    struct { uint32_t Ap[8192]; } c;                                 // 32KB
    struct { float Hs[32][64]; float Ws[64][64]; } e;                // 24KB
};

__global__ void __launch_bounds__(1024, 1)
k_persist(const float* __restrict__ x, const float* __restrict__ v,
          const float* __restrict__ b_dec, int G){
    __shared__ SH sh;
    const int tid = threadIdx.x;
    const int lane = tid & 31, warp = tid >> 5;
    unsigned int bt = (unsigned)G;

    for(int s=0; s<TT; s++){
        // ======== Phase A: attention scores (128 tasks: b x tp4) ========
        for(int task = blockIdx.x; task < 128; task += G){
            int b = task >> 2, tp = task & 3;
            if(tid < HH){
                float a0=0.f, a1=0.f;
                #pragma unroll
                for(int kc=0;kc<8;kc++){
                    a0 += g_decp[((kc*2+0)*BB + b)*HH + tid];
                    a1 += g_decp[((kc*2+1)*BB + b)*HH + tid];
                }
                sh.a.d0[tid]=a0; sh.a.d1[tid]=a1; sh.a.vs[tid]=v[tid];
            }
            __syncthreads();
            #pragma unroll 1
            for(int i=0;i<4;i++){
                int t = tp*128 + warp*4 + i;
                const float* e = &g_enc[(b*TT + t)*HH];
                float s0=0.f, s1=0.f;
                #pragma unroll
                for(int j=0;j<16;j++){
                    int h = lane + j*32;
                    float ev = e[h];
                    float vv = sh.a.vs[h];
                    s0 += vv*fast_tanh(ev + sh.a.d0[h]);
                    s1 += vv*fast_tanh(ev + sh.a.d1[h]);
                }
                s0 = warpSum(s0); s1 = warpSum(s1);
                if(lane==0){
                    g_scores[b*TT + t] = s0;
                    g_scores[(BB + b)*TT + t] = s1;
                }
            }
            __syncthreads();
        }
        gbar(bt); bt += G;

        // ======== Phase B: softmax + context partials (128 tasks: b x tp4) ======
        for(int task = blockIdx.x; task < 128; task += G){
            int b = task >> 2, tp = task & 3;
            int t0 = tp*128;
            if(tid < TT){
                sh.b.w0[tid] = g_scores[b*TT + tid];
                sh.b.w1[tid] = g_scores[(BB+b)*TT + tid];
            }
            __syncthreads();
            if(warp < 16){
                float m0 = warpMax(sh.b.w0[tid]);
                float m1 = warpMax(sh.b.w1[tid]);
                if(lane==0){ sh.b.red0[warp]=m0; sh.b.red1[warp]=m1; }
            }
            __syncthreads();
            float m0 = sh.b.red0[0], m1 = sh.b.red1[0];
            #pragma unroll
            for(int j=1;j<16;j++){ m0=fmaxf(m0,sh.b.red0[j]); m1=fmaxf(m1,sh.b.red1[j]); }
            __syncthreads();
            if(warp < 16){
                float e0 = __expf(sh.b.w0[tid]-m0); sh.b.w0[tid]=e0;
                float e1 = __expf(sh.b.w1[tid]-m1); sh.b.w1[tid]=e1;
                float z0 = warpSum(e0), z1 = warpSum(e1);
                if(lane==0){ sh.b.red0[warp]=z0; sh.b.red1[warp]=z1; }
            }
            __syncthreads();
            float z0=0.f, z1=0.f;
            #pragma unroll
            for(int j=0;j<16;j++){ z0+=sh.b.red0[j]; z1+=sh.b.red1[j]; }
            float inv0 = __fdividef(1.0f, z0), inv1 = __fdividef(1.0f, z1);

            if(tid < DD){
                float a0=0.f, a1=0.f;
                #pragma unroll 8
                for(int t=0;t<128;t++){
                    float ww0 = sh.b.w0[t0+t]*inv0;
                    float ww1 = sh.b.w1[t0+t]*inv1;
                    float xv = x[(long)(b*TT + t0 + t)*DD + tid];
                    a0 += ww0*xv; a1 += ww1*xv;
                }
                g_ctxp[((tp*2+0)*BB + b)*DD + tid] = a0;
                g_ctxp[((tp*2+1)*BB + b)*DD + tid] = a1;
            }
            __syncthreads();
        }
        gbar(bt); bt += G;

        // ======== Phase C: gates GEMM via tf32 mma (128 tasks: dir x nt8 x kc8) =
        for(int task = blockIdx.x; task < 128; task += G){
            int dir = task & 1, nt = (task>>1)&7, kc = task>>4;
            int n0 = nt*256, k0 = kc*256;
            int t = dir ? (TT-1-s) : s;

            __syncthreads();
            // ---- fill frag-packed A (32b x 256k, tf32) ----
            #pragma unroll
            for(int r=0;r<8;r++){
                int idx = tid + (r<<10);
                int b = idx>>8, kl = idx&255;
                int k = k0 + kl;
                float val;
                if(kc < 3){
                    val = g_ctxp[((0*2+dir)*BB+b)*DD + k]
                        + g_ctxp[((1*2+dir)*BB+b)*DD + k]
                        + g_ctxp[((2*2+dir)*BB+b)*DD + k]
                        + g_ctxp[((3*2+dir)*BB+b)*DD + k];
                } else if(kc < 6){
                    val = x[(long)(b*TT + t)*DD + (k-768)];
                } else {
                    val = g_h[(dir*BB+b)*HH + (k-1536)];
                }
                uint32_t u = to_tf32(val);
                int ks = kl>>3, klo = kl&7;
                int tg = klo&3, hi = klo>>2;
                int gid = b&7, rh = (b>>3)&1, mt = b>>4;
                int slot = (((mt ^ (ks&1))<<2) | (hi<<1) | rh);
                sh.c.Ap[((ks<<5) + (gid<<2) + tg)*8 + slot] = u;
            }
            __syncthreads();

            int nw = warp>>1, kh = warp&1;
            float acc[2][2][4];
            #pragma unroll
            for(int mt=0;mt<2;mt++)
                #pragma unroll
                for(int j=0;j<2;j++)
                    #pragma unroll
                    for(int r=0;r<4;r++) acc[mt][j][r]=0.f;

            const float2* Bp = (const float2*)g_WcatP + ((size_t)dir<<21);   // dir*256*256*32

            #pragma unroll 4
            for(int ks16=0; ks16<16; ks16++){
                int ksg = (kh<<4) + ks16;
                const uint32_t* ap = &sh.c.Ap[((ksg<<5) + lane)*8];
                int g0 = (ksg&1)<<2;
                uint4 A0 = *(const uint4*)(ap + g0);
                uint4 A1 = *(const uint4*)(ap + (4^g0));
                int k8g = (kc<<5) + ksg;
                #pragma unroll
                for(int j=0;j<2;j++){
                    int n8g = (nt<<5) + (nw<<1) + j;
                    float2 bf = Bp[(((size_t)k8g<<8) + n8g)*32 + lane];
                    uint32_t b0 = __float_as_uint(bf.x);
                    uint32_t b1 = __float_as_uint(bf.y);
                    mma_tf32(acc[0][j], (const uint32_t*)&A0, b0, b1);
                    mma_tf32(acc[1][j], (const uint32_t*)&A1, b0, b1);
                }
            }
            __syncthreads();
            // ---- combine the two k-halves in-block, then store ----
            float* buf = (float*)sh.c.Ap;
            if(kh == 1){
                #pragma unroll
                for(int mt=0;mt<2;mt++)
                    #pragma unroll
                    for(int j=0;j<2;j++)
                        #pragma unroll
                        for(int r=0;r<4;r++)
                            buf[nw*512 + (mt*2+j)*128 + r*32 + lane] = acc[mt][j][r];
            }
            __syncthreads();
            if(kh == 0){
                int gid = lane>>2, tg = lane&3;
                #pragma unroll
                for(int mt=0;mt<2;mt++){
                    #pragma unroll
                    for(int j=0;j<2;j++){
                        const float* bb4 = &buf[nw*512 + (mt*2+j)*128];
                        float c0 = acc[mt][j][0] + bb4[0*32 + lane];
                        float c1 = acc[mt][j][1] + bb4[1*32 + lane];
                        float c2 = acc[mt][j][2] + bb4[2*32 + lane];
                        float c3 = acc[mt][j][3] + bb4[3*32 + lane];
                        int n = n0 + ((nw<<1)+j)*8 + (tg<<1);
                        int br = (mt<<4) + gid;
                        *(float2*)&g_gpart[((long)(kc*2+dir)*BB + br)*N4H + n]     = make_float2(c0,c1);
                        *(float2*)&g_gpart[((long)(kc*2+dir)*BB + br + 8)*N4H + n] = make_float2(c2,c3);
                    }
                }
            }
            __syncthreads();
        }
        gbar(bt); bt += G;

        // ======== Phase D: LSTM pointwise (grid-strided) ========
        for(int idx = blockIdx.x*1024 + tid; idx < 2*BB*HH; idx += G*1024){
            int hc = idx & (HH-1);
            int b  = (idx>>9) & (BB-1);
            int dir = idx>>14;
            int t = dir ? (TT-1-s) : s;
            float4 gs = make_float4(0.f,0.f,0.f,0.f);
            #pragma unroll
            for(int p=0;p<8;p++){
                float4 gp = *(const float4*)&g_gpart[((long)(p*2+dir)*BB + b)*N4H + hc*4];
                gs.x+=gp.x; gs.y+=gp.y; gs.z+=gp.z; gs.w+=gp.w;
            }
            float4 bc = *(const float4*)&g_bcat[dir*N4H + hc*4];
            float ig = sigm(gs.x+bc.x);
            float fg = sigm(gs.y+bc.y);
            float gg = tanh_acc(gs.z+bc.z);
            float og = sigm(gs.w+bc.w);
            int ix = (dir*BB+b)*HH + hc;
            float c = fg*g_c[ix] + ig*gg;
            float h = og*tanh_acc(c);
            g_c[ix]=c; g_h[ix]=h;
            g_hs[((dir*TT+t)*BB + b)*HH + hc] = h;
        }
        gbar(bt); bt += G;

        // ======== Phase E: dec partials (h @ WdecT), 128 tasks: dir x nt8 x kc8 =
        for(int task = blockIdx.x; task < 128; task += G){
            int dir = task & 1, nt = (task>>1)&7, kc = task>>4;
            int n0 = nt*64, k0 = kc*64;
            #pragma unroll
            for(int r=0;r<2;r++){
                int lin = tid + 1024*r;
                int bi = lin>>6, k = lin&63;
                sh.e.Hs[bi][k] = g_h[(dir*BB+bi)*HH + k0 + k];
            }
            #pragma unroll
            for(int r=0;r<4;r++){
                int lin = tid + 1024*r;
                int k = lin>>6, n = lin&63;
                sh.e.Ws[k][n] = g_WdecT[(k0+k)*HH + n0 + n];
            }
            __syncthreads();
            int tb = tid>>5, tn = tid&31;
            float acc0=0.f, acc1=0.f;
            #pragma unroll 8
            for(int k=0;k<64;k++){
                float a = sh.e.Hs[tb][k];
                float2 w2 = *(const float2*)&sh.e.Ws[k][tn*2];
                acc0 += a*w2.x; acc1 += a*w2.y;
            }
            int n = n0 + tn*2;
            float bias0 = (kc==0) ? b_dec[n]   : 0.f;
            float bias1 = (kc==0) ? b_dec[n+1] : 0.f;
            g_decp[((kc*2+dir)*BB + tb)*HH + n]   = acc0 + bias0;
            g_decp[((kc*2+dir)*BB + tb)*HH + n+1] = acc1 + bias1;
            __syncthreads();
        }
        gbar(bt); bt += G;
    }
}

// ---------------- final head ----------------------------------------------------
__global__ void k_head(const float* __restrict__ W_head, const float* __restrict__ b_head,
                       float* __restrict__ out){
    __shared__ float Ws[CC*2*HH];   // 28KB
    int tid = threadIdx.x;
    for(int i=tid;i<CC*2*HH;i+=256) Ws[i] = W_head[i];
    __syncthreads();
    int warp = tid>>5, lane = tid&31;
    int m = blockIdx.x*8 + warp;
    int b = m >> 9, t = m & (TT-1);
    const float* hf = &g_hs[((0*TT+t)*BB + b)*HH];
    const float* hb = &g_hs[((1*TT+t)*BB + b)*HH];
    float acc[CC];
    #pragma unroll
    for(int c=0;c<CC;c++) acc[c]=0.f;
    #pragma unroll 4
    for(int i=0;i<16;i++){
        int k = lane + i*32;
        float vf = hf[k];
        float vb = hb[k];
        #pragma unroll
        for(int c=0;c<CC;c++){
            acc[c] += vf*Ws[c*1024 + k] + vb*Ws[c*1024 + 512 + k];
        }
    }
    float res = 0.f;
    #pragma unroll
    for(int c=0;c<CC;c++){
        float r = warpSum(acc[c]);
        if(lane==c) res = r;
    }
    if(lane < CC) out[m*CC + lane] = res + b_head[lane];
}

// ---------------- launch ----------------
extern "C" void kernel_launch(void* const* d_in, const int* in_sizes, int n_in,
                              void* d_out, int out_size){
    const float* x      = (const float*)d_in[0];
    const float* Wf_ih  = (const float*)d_in[1];
    const float* Wf_hh  = (const float*)d_in[2];
    const float* bf     = (const float*)d_in[3];
    const float* Wb_ih  = (const float*)d_in[4];
    const float* Wb_hh  = (const float*)d_in[5];
    const float* bb     = (const float*)d_in[6];
    const float* W_enc  = (const float*)d_in[7];
    const float* b_enc  = (const float*)d_in[8];
    const float* W_dec  = (const float*)d_in[9];
    const float* b_dec  = (const float*)d_in[10];
    const float* v      = (const float*)d_in[11];
    const float* W_head = (const float*)d_in[12];
    const float* b_head = (const float*)d_in[13];
    float* out = (float*)d_out;

    int dev = 0;
    cudaGetDevice(&dev);
    int nsm = 128;
    cudaDeviceGetAttribute(&nsm, cudaDevAttrMultiProcessorCount, dev);
    int G = nsm;

    k_init<<<1024, 256>>>(b_dec);
    k_prep<<<2048, 256>>>(Wf_ih, Wf_hh, bf, Wb_ih, Wb_hh, bb, W_dec);
    k_enc_gemm<<<dim3(8, 256), 256>>>(x, W_enc, b_enc);
    k_persist<<<G, 1024>>>(x, v, b_dec, G);
    k_head<<<2048, 256>>>(W_head, b_head, out);
}

// round 10
// speedup vs baseline: 2.2420x; 1.3863x over previous
#include <cuda_runtime.h>
#include <cuda_bf16.h>
#include <cuda_fp16.h>
#include <cstdint>

#define BB 32
#define TT 512
#define DD 768
#define HH 512
#define CC 7
#define K2 2048          // gates GEMM K = ctx(768) + xt(768) + h(512)
#define N4H 2048         // 4*H

// ---------------- device state (static scratch; no allocations) ----------------
__device__ float g_enc[BB*TT*HH];          // [b][t][h] enc_proj fp32 (33.5MB)
__device__ __half g_xh[BB*TT*DD];          // fp16 copy of x (25MB)
__device__ uint2 g_WcatPh[2*128*256*32];   // frag-packed fp16 weights (16.7MB)
__device__ float g_bcat[2*N4H];            // [dir][jj]
__device__ float g_WdecT[HH*HH];           // [k][n]
__device__ float g_h[2*BB*HH];
__device__ float g_c[2*BB*HH];
__device__ float g_decp[8*2*BB*HH];        // [kc8][dir][b][n] dec partials
__device__ float g_scores[2*BB*TT];        // [dir][b][t]
__device__ float g_ctxp[4*2*BB*DD];        // [part4][dir][b][d]
__device__ float g_gpart[8*2*BB*N4H];      // [kc8][dir][b][jj]  (4.2MB, L2-resident)
__device__ float g_hs[2*TT*BB*HH];         // [dir][t][b][h]
__device__ unsigned int g_arrive;

// ---------------- helpers ----------------
__device__ __forceinline__ float fast_tanh(float x){
    float y; asm("tanh.approx.f32 %0, %1;" : "=f"(y) : "f"(x)); return y;
}
__device__ __forceinline__ float tanh_acc(float x){
    float e = __expf(x + x);
    return 1.0f - __fdividef(2.0f, e + 1.0f);
}
__device__ __forceinline__ float sigm(float x){ return 1.0f/(1.0f+__expf(-x)); }
__device__ __forceinline__ float warpMax(float v){
    #pragma unroll
    for(int o=16;o;o>>=1) v = fmaxf(v, __shfl_xor_sync(0xffffffffu, v, o));
    return v;
}
__device__ __forceinline__ float warpSum(float v){
    #pragma unroll
    for(int o=16;o;o>>=1) v += __shfl_xor_sync(0xffffffffu, v, o);
    return v;
}
__device__ __forceinline__ void mma_f16(float* c, const uint32_t* a, uint32_t b0, uint32_t b1){
    asm volatile("mma.sync.aligned.m16n8k16.row.col.f32.f16.f16.f32 "
                 "{%0,%1,%2,%3}, {%4,%5,%6,%7}, {%8,%9}, {%0,%1,%2,%3};"
                 : "+f"(c[0]), "+f"(c[1]), "+f"(c[2]), "+f"(c[3])
                 : "r"(a[0]), "r"(a[1]), "r"(a[2]), "r"(a[3]), "r"(b0), "r"(b1));
}

// ---------------- grid barrier (monotonic counter, reset by k_init) ------------
__device__ __forceinline__ void gbar(unsigned int target){
    __syncthreads();
    if(threadIdx.x == 0){
        asm volatile("red.release.gpu.global.add.u32 [%0], %1;"
                     :: "l"(&g_arrive), "r"(1u) : "memory");
        unsigned int vv;
        #pragma unroll 1
        do {
            asm volatile("ld.acquire.gpu.u32 %0, [%1];" : "=r"(vv) : "l"(&g_arrive));
            if(vv >= target) break;
            __nanosleep(64);
        } while(true);
    }
    __syncthreads();
}

// ---------------- init ----------------------------------------------------------
__global__ void k_init(const float* __restrict__ b_dec){
    int i = blockIdx.x*blockDim.x + threadIdx.x;
    if(i == 0) g_arrive = 0u;
    if(i < 2*BB*HH){ g_h[i]=0.f; g_c[i]=0.f; }
    if(i < 8*2*BB*HH){
        int kc = i >> 15;
        g_decp[i] = (kc==0) ? b_dec[i & (HH-1)] : 0.f;
    }
}

// ---------------- prep: fp16 frag-packed weights, fp16 x, bcat, WdecT -----------
__global__ void k_prep(const float* __restrict__ Wf_ih, const float* __restrict__ Wf_hh,
                       const float* __restrict__ bf,
                       const float* __restrict__ Wb_ih, const float* __restrict__ Wb_hh,
                       const float* __restrict__ bb,
                       const float* __restrict__ W_dec,
                       const float* __restrict__ x){
    int tid0 = blockIdx.x*blockDim.x + threadIdx.x;
    int stride = gridDim.x*blockDim.x;
    // packed items: [dir][k16 128][n8 256][lane 32] -> uint2 (b0,b1)
    for(int i = tid0; i < 2*128*256*32; i += stride){
        int lane = i & 31;
        int n8 = (i>>5) & 255;
        int k16 = (i>>13) & 127;
        int dir = (i>>20) & 1;
        int gq = lane>>2, tq = lane&3;
        int n = n8*8 + gq;                        // jj (interleaved gate index)
        int j = ((n&3)<<9) + (n>>2);              // torch row: gate*512 + hcol
        const float* Wih = dir ? Wb_ih : Wf_ih;
        const float* Whh = dir ? Wb_hh : Wf_hh;
        int ka = k16*16 + 2*tq;
        int kb = ka + 8;
        float wa0 = (ka   < 1536) ? Wih[j*1536 + ka]   : Whh[j*512 + (ka-1536)];
        float wa1 = (ka+1 < 1536) ? Wih[j*1536 + ka+1] : Whh[j*512 + (ka+1-1536)];
        float wb0 = (kb   < 1536) ? Wih[j*1536 + kb]   : Whh[j*512 + (kb-1536)];
        float wb1 = (kb+1 < 1536) ? Wih[j*1536 + kb+1] : Whh[j*512 + (kb+1-1536)];
        __half2 h0 = __floats2half2_rn(wa0, wa1);
        __half2 h1 = __floats2half2_rn(wb0, wb1);
        g_WcatPh[i] = make_uint2(*(uint32_t*)&h0, *(uint32_t*)&h1);
    }
    // fp16 copy of x
    for(int i = tid0; i < BB*TT*DD; i += stride){
        g_xh[i] = __float2half(x[i]);
    }
    if(tid0 < 2*N4H){
        int jj = tid0 & (N4H-1); int dir = tid0 >> 11;
        int j = ((jj&3)<<9) + (jj>>2);
        g_bcat[tid0] = dir ? bb[j] : bf[j];
    }
    if(tid0 < HH*HH){
        int n = tid0 & (HH-1); int k = tid0 >> 9;
        g_WdecT[k*HH + n] = W_dec[n*HH + k];
    }
}

// ---------------- enc_proj GEMM (fp32 out) --------------------------------------
__global__ void k_enc_gemm(const float* __restrict__ A, const float* __restrict__ Bm,
                           const float* __restrict__ bias){
    __shared__ float As[16][68];
    __shared__ float Bs[16][68];
    const int Kk = DD, Nn = HH;
    int n0 = blockIdx.x*64, m0 = blockIdx.y*64;
    int tid = threadIdx.x;
    int tm = tid>>4, tn = tid&15;
    float acc[4][4];
    #pragma unroll
    for(int i=0;i<4;i++)
        #pragma unroll
        for(int j=0;j<4;j++) acc[i][j] = bias[n0 + tn*4 + j];

    int lrow = tid>>2, lkq = (tid&3)*4;
    for(int k0=0;k0<Kk;k0+=16){
        float4 av = *(const float4*)&A[(long)(m0+lrow)*Kk + k0 + lkq];
        float4 bv = *(const float4*)&Bm[(long)(n0+lrow)*Kk + k0 + lkq];
        __syncthreads();
        As[lkq+0][lrow]=av.x; As[lkq+1][lrow]=av.y; As[lkq+2][lrow]=av.z; As[lkq+3][lrow]=av.w;
        Bs[lkq+0][lrow]=bv.x; Bs[lkq+1][lrow]=bv.y; Bs[lkq+2][lrow]=bv.z; Bs[lkq+3][lrow]=bv.w;
        __syncthreads();
        #pragma unroll
        for(int kk=0;kk<16;kk++){
            float4 a4 = *(const float4*)&As[kk][tm*4];
            float4 b4 = *(const float4*)&Bs[kk][tn*4];
            float aa[4] = {a4.x,a4.y,a4.z,a4.w};
            float bb4[4] = {b4.x,b4.y,b4.z,b4.w};
            #pragma unroll
            for(int i=0;i<4;i++)
                #pragma unroll
                for(int j=0;j<4;j++) acc[i][j] += aa[i]*bb4[j];
        }
    }
    #pragma unroll
    for(int i=0;i<4;i++)
        #pragma unroll
        for(int j=0;j<4;j++)
            g_enc[(long)(m0+tm*4+i)*Nn + n0 + tn*4 + j] = acc[i][j];
}

// ---------------- persistent recurrent kernel (1024 threads/block) --------------
union SH {
    struct { float d0[HH], d1[HH], vs[HH]; } a;                      // 6KB
    struct { float w0[TT], w1[TT]; float red0[16], red1[16]; } b;    // 4.1KB
    struct { uint32_t Ap[8192]; } c;                                 // 32KB (A frags use 16KB)
    struct { float Hs[32][64]; float Ws[64][64]; } e;                // 24KB
};

__global__ void __launch_bounds__(1024, 1)
k_persist(const float* __restrict__ x, const float* __restrict__ v,
          const float* __restrict__ b_dec, int G){
    __shared__ SH sh;
    const int tid = threadIdx.x;
    const int lane = tid & 31, warp = tid >> 5;
    unsigned int bt = (unsigned)G;

    for(int s=0; s<TT; s++){
        // ======== Phase A: attention scores (128 tasks: b x tp4), fp32 enc ======
        for(int task = blockIdx.x; task < 128; task += G){
            int b = task >> 2, tp = task & 3;
            if(tid < HH){
                float a0=0.f, a1=0.f;
                #pragma unroll
                for(int kc=0;kc<8;kc++){
                    a0 += g_decp[((kc*2+0)*BB + b)*HH + tid];
                    a1 += g_decp[((kc*2+1)*BB + b)*HH + tid];
                }
                sh.a.d0[tid]=a0; sh.a.d1[tid]=a1; sh.a.vs[tid]=v[tid];
            }
            __syncthreads();
            #pragma unroll 1
            for(int i=0;i<4;i++){
                int t = tp*128 + warp*4 + i;
                const float* e = &g_enc[(b*TT + t)*HH];
                float s0=0.f, s1=0.f;
                #pragma unroll
                for(int j=0;j<16;j++){
                    int h = lane + j*32;
                    float ev = e[h];
                    float vv = sh.a.vs[h];
                    s0 += vv*fast_tanh(ev + sh.a.d0[h]);
                    s1 += vv*fast_tanh(ev + sh.a.d1[h]);
                }
                s0 = warpSum(s0); s1 = warpSum(s1);
                if(lane==0){
                    g_scores[b*TT + t] = s0;
                    g_scores[(BB + b)*TT + t] = s1;
                }
            }
            __syncthreads();
        }
        gbar(bt); bt += G;

        // ======== Phase B: softmax + context partials (128 tasks: b x tp4) ======
        for(int task = blockIdx.x; task < 128; task += G){
            int b = task >> 2, tp = task & 3;
            int t0 = tp*128;
            if(tid < TT){
                sh.b.w0[tid] = g_scores[b*TT + tid];
                sh.b.w1[tid] = g_scores[(BB+b)*TT + tid];
            }
            __syncthreads();
            if(warp < 16){
                float m0 = warpMax(sh.b.w0[tid]);
                float m1 = warpMax(sh.b.w1[tid]);
                if(lane==0){ sh.b.red0[warp]=m0; sh.b.red1[warp]=m1; }
            }
            __syncthreads();
            float m0 = sh.b.red0[0], m1 = sh.b.red1[0];
            #pragma unroll
            for(int j=1;j<16;j++){ m0=fmaxf(m0,sh.b.red0[j]); m1=fmaxf(m1,sh.b.red1[j]); }
            __syncthreads();
            if(warp < 16){
                float e0 = __expf(sh.b.w0[tid]-m0); sh.b.w0[tid]=e0;
                float e1 = __expf(sh.b.w1[tid]-m1); sh.b.w1[tid]=e1;
                float z0 = warpSum(e0), z1 = warpSum(e1);
                if(lane==0){ sh.b.red0[warp]=z0; sh.b.red1[warp]=z1; }
            }
            __syncthreads();
            float z0=0.f, z1=0.f;
            #pragma unroll
            for(int j=0;j<16;j++){ z0+=sh.b.red0[j]; z1+=sh.b.red1[j]; }
            float inv0 = __fdividef(1.0f, z0), inv1 = __fdividef(1.0f, z1);

            if(tid < 384){
                const __half2* xb = (const __half2*)&g_xh[(long)(b*TT + t0)*DD] + tid;
                float a0x=0.f, a0y=0.f, a1x=0.f, a1y=0.f;
                #pragma unroll 8
                for(int t=0;t<128;t++){
                    float ww0 = sh.b.w0[t0+t]*inv0;
                    float ww1 = sh.b.w1[t0+t]*inv1;
                    float2 xv = __half22float2(xb[(long)t*384]);
                    a0x += ww0*xv.x; a0y += ww0*xv.y;
                    a1x += ww1*xv.x; a1y += ww1*xv.y;
                }
                *(float2*)&g_ctxp[((tp*2+0)*BB + b)*DD + tid*2] = make_float2(a0x, a0y);
                *(float2*)&g_ctxp[((tp*2+1)*BB + b)*DD + tid*2] = make_float2(a1x, a1y);
            }
            __syncthreads();
        }
        gbar(bt); bt += G;

        // ======== Phase C: gates GEMM via fp16 mma (128 tasks: dir x nt8 x kc8) =
        for(int task = blockIdx.x; task < 128; task += G){
            int dir = task & 1, nt = (task>>1)&7, kc = task>>4;
            int n0 = nt*256, k0 = kc*256;
            int t = dir ? (TT-1-s) : s;

            __syncthreads();
            // ---- fill frag-packed A (32b x 256k, fp16 pairs) ----
            #pragma unroll
            for(int r=0;r<4;r++){
                int idx = tid + (r<<10);
                int b = idx>>7, kp = idx&127;
                int k = k0 + kp*2;
                float v0, v1;
                if(kc < 3){
                    v0 = g_ctxp[((0*2+dir)*BB+b)*DD + k]
                       + g_ctxp[((1*2+dir)*BB+b)*DD + k]
                       + g_ctxp[((2*2+dir)*BB+b)*DD + k]
                       + g_ctxp[((3*2+dir)*BB+b)*DD + k];
                    v1 = g_ctxp[((0*2+dir)*BB+b)*DD + k+1]
                       + g_ctxp[((1*2+dir)*BB+b)*DD + k+1]
                       + g_ctxp[((2*2+dir)*BB+b)*DD + k+1]
                       + g_ctxp[((3*2+dir)*BB+b)*DD + k+1];
                } else if(kc < 6){
                    v0 = __half2float(g_xh[(long)(b*TT + t)*DD + (k-768)]);
                    v1 = __half2float(g_xh[(long)(b*TT + t)*DD + (k+1-768)]);
                } else {
                    v0 = g_h[(dir*BB+b)*HH + (k-1536)];
                    v1 = g_h[(dir*BB+b)*HH + (k+1-1536)];
                }
                __half2 hv = __floats2half2_rn(v0, v1);
                int ks = kp>>3, kkp = kp&7;
                int tq = kkp&3, khalf = kkp>>2;
                int mt = b>>4, rin = b&15, gq = rin&7, hi = rin>>3;
                sh.c.Ap[(((ks*2+mt)*32 + gq*4 + tq)<<2) + khalf*2 + hi] = *(uint32_t*)&hv;
            }
            __syncthreads();

            int nw = warp>>1, kh = warp&1;
            float acc[2][2][4];
            #pragma unroll
            for(int mt=0;mt<2;mt++)
                #pragma unroll
                for(int j=0;j<2;j++)
                    #pragma unroll
                    for(int r=0;r<4;r++) acc[mt][j][r]=0.f;

            const uint2* Bp = g_WcatPh + ((size_t)dir*128*256*32);

            #pragma unroll
            for(int i8=0;i8<8;i8++){
                int ksg = (kh<<3) + i8;
                uint4 A0 = *(const uint4*)&sh.c.Ap[((ksg*2+0)*32 + lane)*4];
                uint4 A1 = *(const uint4*)&sh.c.Ap[((ksg*2+1)*32 + lane)*4];
                int k16g = (kc<<4) + ksg;
                #pragma unroll
                for(int j=0;j<2;j++){
                    int n8g = (nt<<5) + (nw<<1) + j;
                    uint2 bb2 = Bp[((size_t)k16g*256 + n8g)*32 + lane];
                    mma_f16(acc[0][j], (const uint32_t*)&A0, bb2.x, bb2.y);
                    mma_f16(acc[1][j], (const uint32_t*)&A1, bb2.x, bb2.y);
                }
            }
            __syncthreads();
            // ---- combine the two k-halves in-block, then store ----
            float* buf = (float*)sh.c.Ap;
            if(kh == 1){
                #pragma unroll
                for(int mt=0;mt<2;mt++)
                    #pragma unroll
                    for(int j=0;j<2;j++)
                        #pragma unroll
                        for(int r=0;r<4;r++)
                            buf[nw*512 + (mt*2+j)*128 + r*32 + lane] = acc[mt][j][r];
            }
            __syncthreads();
            if(kh == 0){
                int gid = lane>>2, tg = lane&3;
                #pragma unroll
                for(int mt=0;mt<2;mt++){
                    #pragma unroll
                    for(int j=0;j<2;j++){
                        const float* bb4 = &buf[nw*512 + (mt*2+j)*128];
                        float c0 = acc[mt][j][0] + bb4[0*32 + lane];
                        float c1 = acc[mt][j][1] + bb4[1*32 + lane];
                        float c2 = acc[mt][j][2] + bb4[2*32 + lane];
                        float c3 = acc[mt][j][3] + bb4[3*32 + lane];
                        int n = n0 + ((nw<<1)+j)*8 + (tg<<1);
                        int br = (mt<<4) + gid;
                        *(float2*)&g_gpart[((long)(kc*2+dir)*BB + br)*N4H + n]     = make_float2(c0,c1);
                        *(float2*)&g_gpart[((long)(kc*2+dir)*BB + br + 8)*N4H + n] = make_float2(c2,c3);
                    }
                }
            }
            __syncthreads();
        }
        gbar(bt); bt += G;

        // ======== Phase D: LSTM pointwise (grid-strided) ========
        for(int idx = blockIdx.x*1024 + tid; idx < 2*BB*HH; idx += G*1024){
            int hc = idx & (HH-1);
            int b  = (idx>>9) & (BB-1);
            int dir = idx>>14;
            int t = dir ? (TT-1-s) : s;
            float4 gs = make_float4(0.f,0.f,0.f,0.f);
            #pragma unroll
            for(int p=0;p<8;p++){
                float4 gp = *(const float4*)&g_gpart[((long)(p*2+dir)*BB + b)*N4H + hc*4];
                gs.x+=gp.x; gs.y+=gp.y; gs.z+=gp.z; gs.w+=gp.w;
            }
            float4 bc = *(const float4*)&g_bcat[dir*N4H + hc*4];
            float ig = sigm(gs.x+bc.x);
            float fg = sigm(gs.y+bc.y);
            float gg = tanh_acc(gs.z+bc.z);
            float og = sigm(gs.w+bc.w);
            int ix = (dir*BB+b)*HH + hc;
            float c = fg*g_c[ix] + ig*gg;
            float h = og*tanh_acc(c);
            g_c[ix]=c; g_h[ix]=h;
            g_hs[((dir*TT+t)*BB + b)*HH + hc] = h;
        }
        gbar(bt); bt += G;

        // ======== Phase E: dec partials (h @ WdecT), 128 tasks: dir x nt8 x kc8 =
        for(int task = blockIdx.x; task < 128; task += G){
            int dir = task & 1, nt = (task>>1)&7, kc = task>>4;
            int n0 = nt*64, k0 = kc*64;
            #pragma unroll
            for(int r=0;r<2;r++){
                int lin = tid + 1024*r;
                int bi = lin>>6, k = lin&63;
                sh.e.Hs[bi][k] = g_h[(dir*BB+bi)*HH + k0 + k];
            }
            #pragma unroll
            for(int r=0;r<4;r++){
                int lin = tid + 1024*r;
                int k = lin>>6, n = lin&63;
                sh.e.Ws[k][n] = g_WdecT[(k0+k)*HH + n0 + n];
            }
            __syncthreads();
            int tb = tid>>5, tn = tid&31;
            float acc0=0.f, acc1=0.f;
            #pragma unroll 8
            for(int k=0;k<64;k++){
                float a = sh.e.Hs[tb][k];
                float2 w2 = *(const float2*)&sh.e.Ws[k][tn*2];
                acc0 += a*w2.x; acc1 += a*w2.y;
            }
            int n = n0 + tn*2;
            float bias0 = (kc==0) ? b_dec[n]   : 0.f;
            float bias1 = (kc==0) ? b_dec[n+1] : 0.f;
            g_decp[((kc*2+dir)*BB + tb)*HH + n]   = acc0 + bias0;
            g_decp[((kc*2+dir)*BB + tb)*HH + n+1] = acc1 + bias1;
            __syncthreads();
        }
        gbar(bt); bt += G;
    }
}

// ---------------- final head ----------------------------------------------------
__global__ void k_head(const float* __restrict__ W_head, const float* __restrict__ b_head,
                       float* __restrict__ out){
    __shared__ float Ws[CC*2*HH];   // 28KB
    int tid = threadIdx.x;
    for(int i=tid;i<CC*2*HH;i+=256) Ws[i] = W_head[i];
    __syncthreads();
    int warp = tid>>5, lane = tid&31;
    int m = blockIdx.x*8 + warp;
    int b = m >> 9, t = m & (TT-1);
    const float* hf = &g_hs[((0*TT+t)*BB + b)*HH];
    const float* hb = &g_hs[((1*TT+t)*BB + b)*HH];
    float acc[CC];
    #pragma unroll
    for(int c=0;c<CC;c++) acc[c]=0.f;
    #pragma unroll 4
    for(int i=0;i<16;i++){
        int k = lane + i*32;
        float vf = hf[k];
        float vb = hb[k];
        #pragma unroll
        for(int c=0;c<CC;c++){
            acc[c] += vf*Ws[c*1024 + k] + vb*Ws[c*1024 + 512 + k];
        }
    }
    float res = 0.f;
    #pragma unroll
    for(int c=0;c<CC;c++){
        float r = warpSum(acc[c]);
        if(lane==c) res = r;
    }
    if(lane < CC) out[m*CC + lane] = res + b_head[lane];
}

// ---------------- launch ----------------
extern "C" void kernel_launch(void* const* d_in, const int* in_sizes, int n_in,
                              void* d_out, int out_size){
    const float* x      = (const float*)d_in[0];
    const float* Wf_ih  = (const float*)d_in[1];
    const float* Wf_hh  = (const float*)d_in[2];
    const float* bf     = (const float*)d_in[3];
    const float* Wb_ih  = (const float*)d_in[4];
    const float* Wb_hh  = (const float*)d_in[5];
    const float* bb     = (const float*)d_in[6];
    const float* W_enc  = (const float*)d_in[7];
    const float* b_enc  = (const float*)d_in[8];
    const float* W_dec  = (const float*)d_in[9];
    const float* b_dec  = (const float*)d_in[10];
    const float* v      = (const float*)d_in[11];
    const float* W_head = (const float*)d_in[12];
    const float* b_head = (const float*)d_in[13];
    float* out = (float*)d_out;

    int dev = 0;
    cudaGetDevice(&dev);
    int nsm = 128;
    cudaDeviceGetAttribute(&nsm, cudaDevAttrMultiProcessorCount, dev);
    int G = nsm;

    k_init<<<1024, 256>>>(b_dec);
    k_prep<<<2048, 256>>>(Wf_ih, Wf_hh, bf, Wb_ih, Wb_hh, bb, W_dec, x);
    k_enc_gemm<<<dim3(8, 256), 256>>>(x, W_enc, b_enc);
    k_persist<<<G, 1024>>>(x, v, b_dec, G);
    k_head<<<2048, 256>>>(W_head, b_head, out);
}

// round 11
// speedup vs baseline: 3.0396x; 1.3558x over previous
#include <cuda_runtime.h>
#include <cuda_bf16.h>
#include <cuda_fp16.h>
#include <cstdint>

#define BB 32
#define TT 512
#define DD 768
#define HH 512
#define CC 7
#define K2 2048          // gates GEMM K = ctx(768) + xt(768) + h(512)
#define N4H 2048         // 4*H

// ---------------- device state (static scratch; no allocations) ----------------
__device__ float g_enc[BB*TT*HH];          // [b][t][h] enc_proj fp32 (33.5MB)
__device__ __half g_xh[BB*TT*DD];          // fp16 copy of x (25MB)
__device__ uint2 g_WcatPh[2*128*256*32];   // frag-packed fp16 weights (16.7MB)
__device__ float g_bcat[2*N4H];            // [dir][jj]
__device__ float g_WdecT[HH*HH];           // [k][n]
__device__ float g_h[2*BB*HH];
__device__ float g_c[2*BB*HH];
__device__ float g_decp[8*2*BB*HH];        // [kc8][dir][b][n] dec partials
__device__ float g_mp[2*4*2*BB];           // ping-pong partial maxes [par][tp][dir][b]
__device__ float g_zp[4*2*BB];             // partial Z [tp][dir][b]
__device__ float g_ctxp[4*2*BB*DD];        // [part4][dir][b][d] (UNNORMALIZED)
__device__ float g_gpart[8*2*BB*N4H];      // [kc8][dir][b][jj]  (4.2MB, L2-resident)
__device__ float g_hs[2*TT*BB*HH];         // [dir][t][b][h]
__device__ unsigned int g_arrive;

// ---------------- helpers ----------------
__device__ __forceinline__ float fast_tanh(float x){
    float y; asm("tanh.approx.f32 %0, %1;" : "=f"(y) : "f"(x)); return y;
}
__device__ __forceinline__ float tanh_acc(float x){
    float e = __expf(x + x);
    return 1.0f - __fdividef(2.0f, e + 1.0f);
}
__device__ __forceinline__ float sigm(float x){ return 1.0f/(1.0f+__expf(-x)); }
__device__ __forceinline__ float warpMax(float v){
    #pragma unroll
    for(int o=16;o;o>>=1) v = fmaxf(v, __shfl_xor_sync(0xffffffffu, v, o));
    return v;
}
__device__ __forceinline__ float warpSum(float v){
    #pragma unroll
    for(int o=16;o;o>>=1) v += __shfl_xor_sync(0xffffffffu, v, o);
    return v;
}
__device__ __forceinline__ void mma_f16(float* c, const uint32_t* a, uint32_t b0, uint32_t b1){
    asm volatile("mma.sync.aligned.m16n8k16.row.col.f32.f16.f16.f32 "
                 "{%0,%1,%2,%3}, {%4,%5,%6,%7}, {%8,%9}, {%0,%1,%2,%3};"
                 : "+f"(c[0]), "+f"(c[1]), "+f"(c[2]), "+f"(c[3])
                 : "r"(a[0]), "r"(a[1]), "r"(a[2]), "r"(a[3]), "r"(b0), "r"(b1));
}

// ---------------- grid barrier (monotonic counter, busy spin) ------------------
__device__ __forceinline__ void gbar(unsigned int target){
    __syncthreads();
    if(threadIdx.x == 0){
        asm volatile("red.release.gpu.global.add.u32 [%0], %1;"
                     :: "l"(&g_arrive), "r"(1u) : "memory");
        unsigned int vv;
        #pragma unroll 1
        do {
            asm volatile("ld.acquire.gpu.u32 %0, [%1];" : "=r"(vv) : "l"(&g_arrive));
        } while(vv < target);
    }
    __syncthreads();
}

// ---------------- init ----------------------------------------------------------
__global__ void k_init(const float* __restrict__ b_dec){
    int i = blockIdx.x*blockDim.x + threadIdx.x;
    if(i == 0) g_arrive = 0u;
    if(i < 2*4*2*BB) g_mp[i] = 0.f;
    if(i < 4*2*BB) g_zp[i] = 1.f;
    if(i < 2*BB*HH){ g_h[i]=0.f; g_c[i]=0.f; }
    if(i < 8*2*BB*HH){
        int kc = i >> 15;
        g_decp[i] = (kc==0) ? b_dec[i & (HH-1)] : 0.f;
    }
}

// ---------------- prep: fp16 frag-packed weights, fp16 x, bcat, WdecT -----------
__global__ void k_prep(const float* __restrict__ Wf_ih, const float* __restrict__ Wf_hh,
                       const float* __restrict__ bf,
                       const float* __restrict__ Wb_ih, const float* __restrict__ Wb_hh,
                       const float* __restrict__ bb,
                       const float* __restrict__ W_dec,
                       const float* __restrict__ x){
    int tid0 = blockIdx.x*blockDim.x + threadIdx.x;
    int stride = gridDim.x*blockDim.x;
    // packed items: [dir][k16 128][n8 256][lane 32] -> uint2 (b0,b1)
    for(int i = tid0; i < 2*128*256*32; i += stride){
        int lane = i & 31;
        int n8 = (i>>5) & 255;
        int k16 = (i>>13) & 127;
        int dir = (i>>20) & 1;
        int gq = lane>>2, tq = lane&3;
        int n = n8*8 + gq;                        // jj (interleaved gate index)
        int j = ((n&3)<<9) + (n>>2);              // torch row: gate*512 + hcol
        const float* Wih = dir ? Wb_ih : Wf_ih;
        const float* Whh = dir ? Wb_hh : Wf_hh;
        int ka = k16*16 + 2*tq;
        int kb = ka + 8;
        float wa0 = (ka   < 1536) ? Wih[j*1536 + ka]   : Whh[j*512 + (ka-1536)];
        float wa1 = (ka+1 < 1536) ? Wih[j*1536 + ka+1] : Whh[j*512 + (ka+1-1536)];
        float wb0 = (kb   < 1536) ? Wih[j*1536 + kb]   : Whh[j*512 + (kb-1536)];
        float wb1 = (kb+1 < 1536) ? Wih[j*1536 + kb+1] : Whh[j*512 + (kb+1-1536)];
        __half2 h0 = __floats2half2_rn(wa0, wa1);
        __half2 h1 = __floats2half2_rn(wb0, wb1);
        g_WcatPh[i] = make_uint2(*(uint32_t*)&h0, *(uint32_t*)&h1);
    }
    // fp16 copy of x
    for(int i = tid0; i < BB*TT*DD; i += stride){
        g_xh[i] = __float2half(x[i]);
    }
    if(tid0 < 2*N4H){
        int jj = tid0 & (N4H-1); int dir = tid0 >> 11;
        int j = ((jj&3)<<9) + (jj>>2);
        g_bcat[tid0] = dir ? bb[j] : bf[j];
    }
    if(tid0 < HH*HH){
        int n = tid0 & (HH-1); int k = tid0 >> 9;
        g_WdecT[k*HH + n] = W_dec[n*HH + k];
    }
}

// ---------------- enc_proj GEMM (fp32 out) --------------------------------------
__global__ void k_enc_gemm(const float* __restrict__ A, const float* __restrict__ Bm,
                           const float* __restrict__ bias){
    __shared__ float As[16][68];
    __shared__ float Bs[16][68];
    const int Kk = DD, Nn = HH;
    int n0 = blockIdx.x*64, m0 = blockIdx.y*64;
    int tid = threadIdx.x;
    int tm = tid>>4, tn = tid&15;
    float acc[4][4];
    #pragma unroll
    for(int i=0;i<4;i++)
        #pragma unroll
        for(int j=0;j<4;j++) acc[i][j] = bias[n0 + tn*4 + j];

    int lrow = tid>>2, lkq = (tid&3)*4;
    for(int k0=0;k0<Kk;k0+=16){
        float4 av = *(const float4*)&A[(long)(m0+lrow)*Kk + k0 + lkq];
        float4 bv = *(const float4*)&Bm[(long)(n0+lrow)*Kk + k0 + lkq];
        __syncthreads();
        As[lkq+0][lrow]=av.x; As[lkq+1][lrow]=av.y; As[lkq+2][lrow]=av.z; As[lkq+3][lrow]=av.w;
        Bs[lkq+0][lrow]=bv.x; Bs[lkq+1][lrow]=bv.y; Bs[lkq+2][lrow]=bv.z; Bs[lkq+3][lrow]=bv.w;
        __syncthreads();
        #pragma unroll
        for(int kk=0;kk<16;kk++){
            float4 a4 = *(const float4*)&As[kk][tm*4];
            float4 b4 = *(const float4*)&Bs[kk][tn*4];
            float aa[4] = {a4.x,a4.y,a4.z,a4.w};
            float bb4[4] = {b4.x,b4.y,b4.z,b4.w};
            #pragma unroll
            for(int i=0;i<4;i++)
                #pragma unroll
                for(int j=0;j<4;j++) acc[i][j] += aa[i]*bb4[j];
        }
    }
    #pragma unroll
    for(int i=0;i<4;i++)
        #pragma unroll
        for(int j=0;j<4;j++)
            g_enc[(long)(m0+tm*4+i)*Nn + n0 + tn*4 + j] = acc[i][j];
}

// ---------------- persistent recurrent kernel (1024 threads/block) --------------
union SH {
    struct { float d0[HH], d1[HH], vs[HH];
             float sw0[128], sw1[128];
             float red0[8], red1[8]; } a;                            // ~7.2KB
    struct { uint32_t Ap[8192]; float zinv[32]; } c;                 // 32.1KB
    struct { float Hs[32][64]; float Ws[64][64]; } e;                // 24KB
};

__global__ void __launch_bounds__(1024, 1)
k_persist(const float* __restrict__ x, const float* __restrict__ v,
          const float* __restrict__ b_dec, int G){
    __shared__ SH sh;
    const int tid = threadIdx.x;
    const int lane = tid & 31, warp = tid >> 5;
    unsigned int bt = (unsigned)G;

    for(int s=0; s<TT; s++){
        // ======== Phase AB: scores + stale-max softmax + unnormalized ctx ========
        for(int task = blockIdx.x; task < 128; task += G){
            int b = task >> 2, tp = task & 3;
            int t0 = tp*128;
            if(tid < HH){
                float a0=0.f, a1=0.f;
                #pragma unroll
                for(int kc=0;kc<8;kc++){
                    a0 += g_decp[((kc*2+0)*BB + b)*HH + tid];
                    a1 += g_decp[((kc*2+1)*BB + b)*HH + tid];
                }
                sh.a.d0[tid]=a0; sh.a.d1[tid]=a1; sh.a.vs[tid]=v[tid];
            }
            __syncthreads();
            // scores for this task's 128 timesteps -> smem
            #pragma unroll 1
            for(int i=0;i<4;i++){
                int tl = warp*4 + i;
                const float* e = &g_enc[(b*TT + t0 + tl)*HH];
                float s0=0.f, s1=0.f;
                #pragma unroll
                for(int j=0;j<16;j++){
                    int h = lane + j*32;
                    float ev = e[h];
                    float vv = sh.a.vs[h];
                    s0 += vv*fast_tanh(ev + sh.a.d0[h]);
                    s1 += vv*fast_tanh(ev + sh.a.d1[h]);
                }
                s0 = warpSum(s0); s1 = warpSum(s1);
                if(lane==0){ sh.a.sw0[tl] = s0; sh.a.sw1[tl] = s1; }
            }
            __syncthreads();
            // stale max (from previous step, ping-pong)
            const float* mpr = g_mp + (s&1)*256;
            float m0 = mpr[(0*2+0)*BB+b], m1 = mpr[(0*2+1)*BB+b];
            #pragma unroll
            for(int p=1;p<4;p++){
                m0 = fmaxf(m0, mpr[(p*2+0)*BB+b]);
                m1 = fmaxf(m1, mpr[(p*2+1)*BB+b]);
            }
            // exp + partial Z + local max for next step
            if(tid < 256){
                int tl = tid & 127, dq = tid>>7;
                float sc = dq ? sh.a.sw1[tl] : sh.a.sw0[tl];
                float e = __expf(sc - (dq ? m1 : m0));
                if(dq) sh.a.sw1[tl] = e; else sh.a.sw0[tl] = e;
                float z = warpSum(e);
                float mx = warpMax(sc);
                if(lane==0){ sh.a.red0[warp] = z; sh.a.red1[warp] = mx; }
            }
            __syncthreads();
            if(tid == 0){
                g_zp[(tp*2+0)*BB+b] = sh.a.red0[0]+sh.a.red0[1]+sh.a.red0[2]+sh.a.red0[3];
                g_zp[(tp*2+1)*BB+b] = sh.a.red0[4]+sh.a.red0[5]+sh.a.red0[6]+sh.a.red0[7];
                float* mpw = g_mp + ((s+1)&1)*256;
                mpw[(tp*2+0)*BB+b] = fmaxf(fmaxf(sh.a.red1[0],sh.a.red1[1]),
                                           fmaxf(sh.a.red1[2],sh.a.red1[3]));
                mpw[(tp*2+1)*BB+b] = fmaxf(fmaxf(sh.a.red1[4],sh.a.red1[5]),
                                           fmaxf(sh.a.red1[6],sh.a.red1[7]));
            }
            __syncthreads();
            // unnormalized ctx partials over this task's 128 timesteps
            if(tid < 384){
                const __half2* xb = (const __half2*)&g_xh[(long)(b*TT + t0)*DD] + tid;
                float a0x=0.f, a0y=0.f, a1x=0.f, a1y=0.f;
                #pragma unroll 8
                for(int t=0;t<128;t++){
                    float ww0 = sh.a.sw0[t];
                    float ww1 = sh.a.sw1[t];
                    float2 xv = __half22float2(xb[(long)t*384]);
                    a0x += ww0*xv.x; a0y += ww0*xv.y;
                    a1x += ww1*xv.x; a1y += ww1*xv.y;
                }
                *(float2*)&g_ctxp[((tp*2+0)*BB + b)*DD + tid*2] = make_float2(a0x, a0y);
                *(float2*)&g_ctxp[((tp*2+1)*BB + b)*DD + tid*2] = make_float2(a1x, a1y);
            }
            __syncthreads();
        }
        gbar(bt); bt += G;

        // ======== Phase C: gates GEMM via fp16 mma (128 tasks: dir x nt8 x kc8) =
        for(int task = blockIdx.x; task < 128; task += G){
            int dir = task & 1, nt = (task>>1)&7, kc = task>>4;
            int n0 = nt*256, k0 = kc*256;
            int t = dir ? (TT-1-s) : s;

            __syncthreads();
            if(tid < 32){
                float z = g_zp[(0*2+dir)*BB+tid] + g_zp[(1*2+dir)*BB+tid]
                        + g_zp[(2*2+dir)*BB+tid] + g_zp[(3*2+dir)*BB+tid];
                sh.c.zinv[tid] = 1.0f / z;
            }
            __syncthreads();
            // ---- fill frag-packed A (32b x 256k, fp16 pairs) ----
            #pragma unroll
            for(int r=0;r<4;r++){
                int idx = tid + (r<<10);
                int b = idx>>7, kp = idx&127;
                int k = k0 + kp*2;
                float v0, v1;
                if(kc < 3){
                    float zi = sh.c.zinv[b];
                    v0 = (g_ctxp[((0*2+dir)*BB+b)*DD + k]
                        + g_ctxp[((1*2+dir)*BB+b)*DD + k]
                        + g_ctxp[((2*2+dir)*BB+b)*DD + k]
                        + g_ctxp[((3*2+dir)*BB+b)*DD + k]) * zi;
                    v1 = (g_ctxp[((0*2+dir)*BB+b)*DD + k+1]
                        + g_ctxp[((1*2+dir)*BB+b)*DD + k+1]
                        + g_ctxp[((2*2+dir)*BB+b)*DD + k+1]
                        + g_ctxp[((3*2+dir)*BB+b)*DD + k+1]) * zi;
                } else if(kc < 6){
                    v0 = __half2float(g_xh[(long)(b*TT + t)*DD + (k-768)]);
                    v1 = __half2float(g_xh[(long)(b*TT + t)*DD + (k+1-768)]);
                } else {
                    v0 = g_h[(dir*BB+b)*HH + (k-1536)];
                    v1 = g_h[(dir*BB+b)*HH + (k+1-1536)];
                }
                __half2 hv = __floats2half2_rn(v0, v1);
                int ks = kp>>3, kkp = kp&7;
                int tq = kkp&3, khalf = kkp>>2;
                int mt = b>>4, rin = b&15, gq = rin&7, hi = rin>>3;
                sh.c.Ap[(((ks*2+mt)*32 + gq*4 + tq)<<2) + khalf*2 + hi] = *(uint32_t*)&hv;
            }
            __syncthreads();

            int nw = warp>>1, kh = warp&1;
            float acc[2][2][4];
            #pragma unroll
            for(int mt=0;mt<2;mt++)
                #pragma unroll
                for(int j=0;j<2;j++)
                    #pragma unroll
                    for(int r=0;r<4;r++) acc[mt][j][r]=0.f;

            const uint2* Bp = g_WcatPh + ((size_t)dir*128*256*32);

            #pragma unroll
            for(int i8=0;i8<8;i8++){
                int ksg = (kh<<3) + i8;
                uint4 A0 = *(const uint4*)&sh.c.Ap[((ksg*2+0)*32 + lane)*4];
                uint4 A1 = *(const uint4*)&sh.c.Ap[((ksg*2+1)*32 + lane)*4];
                int k16g = (kc<<4) + ksg;
                #pragma unroll
                for(int j=0;j<2;j++){
                    int n8g = (nt<<5) + (nw<<1) + j;
                    uint2 bb2 = Bp[((size_t)k16g*256 + n8g)*32 + lane];
                    mma_f16(acc[0][j], (const uint32_t*)&A0, bb2.x, bb2.y);
                    mma_f16(acc[1][j], (const uint32_t*)&A1, bb2.x, bb2.y);
                }
            }
            __syncthreads();
            // ---- combine the two k-halves in-block, then store ----
            float* buf = (float*)sh.c.Ap;
            if(kh == 1){
                #pragma unroll
                for(int mt=0;mt<2;mt++)
                    #pragma unroll
                    for(int j=0;j<2;j++)
                        #pragma unroll
                        for(int r=0;r<4;r++)
                            buf[nw*512 + (mt*2+j)*128 + r*32 + lane] = acc[mt][j][r];
            }
            __syncthreads();
            if(kh == 0){
                int gid = lane>>2, tg = lane&3;
                #pragma unroll
                for(int mt=0;mt<2;mt++){
                    #pragma unroll
                    for(int j=0;j<2;j++){
                        const float* bb4 = &buf[nw*512 + (mt*2+j)*128];
                        float c0 = acc[mt][j][0] + bb4[0*32 + lane];
                        float c1 = acc[mt][j][1] + bb4[1*32 + lane];
                        float c2 = acc[mt][j][2] + bb4[2*32 + lane];
                        float c3 = acc[mt][j][3] + bb4[3*32 + lane];
                        int n = n0 + ((nw<<1)+j)*8 + (tg<<1);
                        int br = (mt<<4) + gid;
                        *(float2*)&g_gpart[((long)(kc*2+dir)*BB + br)*N4H + n]     = make_float2(c0,c1);
                        *(float2*)&g_gpart[((long)(kc*2+dir)*BB + br + 8)*N4H + n] = make_float2(c2,c3);
                    }
                }
            }
            __syncthreads();
        }
        gbar(bt); bt += G;

        // ======== Phase D: LSTM pointwise (grid-strided) ========
        for(int idx = blockIdx.x*1024 + tid; idx < 2*BB*HH; idx += G*1024){
            int hc = idx & (HH-1);
            int b  = (idx>>9) & (BB-1);
            int dir = idx>>14;
            int t = dir ? (TT-1-s) : s;
            float4 gs = make_float4(0.f,0.f,0.f,0.f);
            #pragma unroll
            for(int p=0;p<8;p++){
                float4 gp = *(const float4*)&g_gpart[((long)(p*2+dir)*BB + b)*N4H + hc*4];
                gs.x+=gp.x; gs.y+=gp.y; gs.z+=gp.z; gs.w+=gp.w;
            }
            float4 bc = *(const float4*)&g_bcat[dir*N4H + hc*4];
            float ig = sigm(gs.x+bc.x);
            float fg = sigm(gs.y+bc.y);
            float gg = tanh_acc(gs.z+bc.z);
            float og = sigm(gs.w+bc.w);
            int ix = (dir*BB+b)*HH + hc;
            float c = fg*g_c[ix] + ig*gg;
            float h = og*tanh_acc(c);
            g_c[ix]=c; g_h[ix]=h;
            g_hs[((dir*TT+t)*BB + b)*HH + hc] = h;
        }
        gbar(bt); bt += G;

        // ======== Phase E: dec partials (h @ WdecT), 128 tasks: dir x nt8 x kc8 =
        for(int task = blockIdx.x; task < 128; task += G){
            int dir = task & 1, nt = (task>>1)&7, kc = task>>4;
            int n0 = nt*64, k0 = kc*64;
            #pragma unroll
            for(int r=0;r<2;r++){
                int lin = tid + 1024*r;
                int bi = lin>>6, k = lin&63;
                sh.e.Hs[bi][k] = g_h[(dir*BB+bi)*HH + k0 + k];
            }
            #pragma unroll
            for(int r=0;r<4;r++){
                int lin = tid + 1024*r;
                int k = lin>>6, n = lin&63;
                sh.e.Ws[k][n] = g_WdecT[(k0+k)*HH + n0 + n];
            }
            __syncthreads();
            int tb = tid>>5, tn = tid&31;
            float acc0=0.f, acc1=0.f;
            #pragma unroll 8
            for(int k=0;k<64;k++){
                float a = sh.e.Hs[tb][k];
                float2 w2 = *(const float2*)&sh.e.Ws[k][tn*2];
                acc0 += a*w2.x; acc1 += a*w2.y;
            }
            int n = n0 + tn*2;
            float bias0 = (kc==0) ? b_dec[n]   : 0.f;
            float bias1 = (kc==0) ? b_dec[n+1] : 0.f;
            g_decp[((kc*2+dir)*BB + tb)*HH + n]   = acc0 + bias0;
            g_decp[((kc*2+dir)*BB + tb)*HH + n+1] = acc1 + bias1;
            __syncthreads();
        }
        gbar(bt); bt += G;
    }
}

// ---------------- final head ----------------------------------------------------
__global__ void k_head(const float* __restrict__ W_head, const float* __restrict__ b_head,
                       float* __restrict__ out){
    __shared__ float Ws[CC*2*HH];   // 28KB
    int tid = threadIdx.x;
    for(int i=tid;i<CC*2*HH;i+=256) Ws[i] = W_head[i];
    __syncthreads();
    int warp = tid>>5, lane = tid&31;
    int m = blockIdx.x*8 + warp;
    int b = m >> 9, t = m & (TT-1);
    const float* hf = &g_hs[((0*TT+t)*BB + b)*HH];
    const float* hb = &g_hs[((1*TT+t)*BB + b)*HH];
    float acc[CC];
    #pragma unroll
    for(int c=0;c<CC;c++) acc[c]=0.f;
    #pragma unroll 4
    for(int i=0;i<16;i++){
        int k = lane + i*32;
        float vf = hf[k];
        float vb = hb[k];
        #pragma unroll
        for(int c=0;c<CC;c++){
            acc[c] += vf*Ws[c*1024 + k] + vb*Ws[c*1024 + 512 + k];
        }
    }
    float res = 0.f;
    #pragma unroll
    for(int c=0;c<CC;c++){
        float r = warpSum(acc[c]);
        if(lane==c) res = r;
    }
    if(lane < CC) out[m*CC + lane] = res + b_head[lane];
}

// ---------------- launch ----------------
extern "C" void kernel_launch(void* const* d_in, const int* in_sizes, int n_in,
                              void* d_out, int out_size){
    const float* x      = (const float*)d_in[0];
    const float* Wf_ih  = (const float*)d_in[1];
    const float* Wf_hh  = (const float*)d_in[2];
    const float* bf     = (const float*)d_in[3];
    const float* Wb_ih  = (const float*)d_in[4];
    const float* Wb_hh  = (const float*)d_in[5];
    const float* bb     = (const float*)d_in[6];
    const float* W_enc  = (const float*)d_in[7];
    const float* b_enc  = (const float*)d_in[8];
    const float* W_dec  = (const float*)d_in[9];
    const float* b_dec  = (const float*)d_in[10];
    const float* v      = (const float*)d_in[11];
    const float* W_head = (const float*)d_in[12];
    const float* b_head = (const float*)d_in[13];
    float* out = (float*)d_out;

    int dev = 0;
    cudaGetDevice(&dev);
    int nsm = 128;
    cudaDeviceGetAttribute(&nsm, cudaDevAttrMultiProcessorCount, dev);
    int G = nsm;

    k_init<<<1024, 256>>>(b_dec);
    k_prep<<<2048, 256>>>(Wf_ih, Wf_hh, bf, Wb_ih, Wb_hh, bb, W_dec, x);
    k_enc_gemm<<<dim3(8, 256), 256>>>(x, W_enc, b_enc);
    k_persist<<<G, 1024>>>(x, v, b_dec, G);
    k_head<<<2048, 256>>>(W_head, b_head, out);
}

// round 12
// speedup vs baseline: 3.6789x; 1.2103x over previous
#include <cuda_runtime.h>
#include <cuda_bf16.h>
#include <cuda_fp16.h>
#include <cstdint>

#define BB 32
#define TT 512
#define DD 768
#define HH 512
#define CC 7
#define K2 2048          // gates GEMM K = ctx(768) + xt(768) + h(512)
#define N4H 2048         // 4*H

// ---------------- device state (static scratch; no allocations) ----------------
__device__ float g_enc[BB*TT*HH];          // [b][t][h] enc_proj fp32 (33.5MB)
__device__ __half g_xh[BB*TT*DD];          // fp16 copy of x (25MB)
__device__ uint2 g_WcatPh[2*128*256*32];   // frag-packed fp16 weights (16.7MB)
__device__ float g_bcat[2*N4H];            // [dir][jj]
__device__ float g_WdecT[HH*HH];           // [k][n]
__device__ float g_h[2*BB*HH];
__device__ float g_c[2*BB*HH];
__device__ float g_decp[8*2*BB*HH];        // [kc8][dir][b][n] dec partials
__device__ float g_mp[2*4*2*BB];           // ping-pong partial maxes [par][tp][dir][b]
__device__ float g_zp[4*2*BB];             // partial Z [tp][dir][b]
__device__ float g_ctxp[4*2*BB*DD];        // [part4][dir][b][d] (UNNORMALIZED)
__device__ float g_gpart[8*2*BB*N4H];      // [kc8][dir][b][jj]  (4.2MB, L2-resident)
__device__ float g_hs[2*TT*BB*HH];         // [dir][t][b][h]
__device__ unsigned int g_arr[64];         // two barrier counters, 128B apart

// ---------------- helpers ----------------
__device__ __forceinline__ float fast_tanh(float x){
    float y; asm("tanh.approx.f32 %0, %1;" : "=f"(y) : "f"(x)); return y;
}
__device__ __forceinline__ float tanh_acc(float x){
    float e = __expf(x + x);
    return 1.0f - __fdividef(2.0f, e + 1.0f);
}
__device__ __forceinline__ float sigm(float x){ return 1.0f/(1.0f+__expf(-x)); }
__device__ __forceinline__ float warpMax(float v){
    #pragma unroll
    for(int o=16;o;o>>=1) v = fmaxf(v, __shfl_xor_sync(0xffffffffu, v, o));
    return v;
}
__device__ __forceinline__ float warpSum(float v){
    #pragma unroll
    for(int o=16;o;o>>=1) v += __shfl_xor_sync(0xffffffffu, v, o);
    return v;
}
__device__ __forceinline__ void mma_f16(float* c, const uint32_t* a, uint32_t b0, uint32_t b1){
    asm volatile("mma.sync.aligned.m16n8k16.row.col.f32.f16.f16.f32 "
                 "{%0,%1,%2,%3}, {%4,%5,%6,%7}, {%8,%9}, {%0,%1,%2,%3};"
                 : "+f"(c[0]), "+f"(c[1]), "+f"(c[2]), "+f"(c[3])
                 : "r"(a[0]), "r"(a[1]), "r"(a[2]), "r"(a[3]), "r"(b0), "r"(b1));
}

// ---------------- per-domain grid barrier (monotonic, busy spin) ----------------
__device__ __forceinline__ void gbar(int dom, unsigned int target){
    __syncthreads();
    if(threadIdx.x == 0){
        unsigned int* ctr = &g_arr[dom<<5];
        asm volatile("red.release.gpu.global.add.u32 [%0], %1;"
                     :: "l"(ctr), "r"(1u) : "memory");
        unsigned int vv;
        #pragma unroll 1
        do {
            asm volatile("ld.acquire.gpu.u32 %0, [%1];" : "=r"(vv) : "l"(ctr));
        } while(vv < target);
    }
    __syncthreads();
}

// ---------------- init ----------------------------------------------------------
__global__ void k_init(const float* __restrict__ b_dec){
    int i = blockIdx.x*blockDim.x + threadIdx.x;
    if(i < 64) g_arr[i] = 0u;
    if(i < 2*4*2*BB) g_mp[i] = 0.f;
    if(i < 4*2*BB) g_zp[i] = 1.f;
    if(i < 2*BB*HH){ g_h[i]=0.f; g_c[i]=0.f; }
    if(i < 8*2*BB*HH){
        int kc = i >> 15;
        g_decp[i] = (kc==0) ? b_dec[i & (HH-1)] : 0.f;
    }
}

// ---------------- prep: fp16 frag-packed weights, fp16 x, bcat, WdecT -----------
__global__ void k_prep(const float* __restrict__ Wf_ih, const float* __restrict__ Wf_hh,
                       const float* __restrict__ bf,
                       const float* __restrict__ Wb_ih, const float* __restrict__ Wb_hh,
                       const float* __restrict__ bb,
                       const float* __restrict__ W_dec,
                       const float* __restrict__ x){
    int tid0 = blockIdx.x*blockDim.x + threadIdx.x;
    int stride = gridDim.x*blockDim.x;
    // packed items: [dir][k16 128][n8 256][lane 32] -> uint2 (b0,b1)
    for(int i = tid0; i < 2*128*256*32; i += stride){
        int lane = i & 31;
        int n8 = (i>>5) & 255;
        int k16 = (i>>13) & 127;
        int dir = (i>>20) & 1;
        int gq = lane>>2, tq = lane&3;
        int n = n8*8 + gq;                        // jj (interleaved gate index)
        int j = ((n&3)<<9) + (n>>2);              // torch row: gate*512 + hcol
        const float* Wih = dir ? Wb_ih : Wf_ih;
        const float* Whh = dir ? Wb_hh : Wf_hh;
        int ka = k16*16 + 2*tq;
        int kb = ka + 8;
        float wa0 = (ka   < 1536) ? Wih[j*1536 + ka]   : Whh[j*512 + (ka-1536)];
        float wa1 = (ka+1 < 1536) ? Wih[j*1536 + ka+1] : Whh[j*512 + (ka+1-1536)];
        float wb0 = (kb   < 1536) ? Wih[j*1536 + kb]   : Whh[j*512 + (kb-1536)];
        float wb1 = (kb+1 < 1536) ? Wih[j*1536 + kb+1] : Whh[j*512 + (kb+1-1536)];
        __half2 h0 = __floats2half2_rn(wa0, wa1);
        __half2 h1 = __floats2half2_rn(wb0, wb1);
        g_WcatPh[i] = make_uint2(*(uint32_t*)&h0, *(uint32_t*)&h1);
    }
    for(int i = tid0; i < BB*TT*DD; i += stride){
        g_xh[i] = __float2half(x[i]);
    }
    if(tid0 < 2*N4H){
        int jj = tid0 & (N4H-1); int dir = tid0 >> 11;
        int j = ((jj&3)<<9) + (jj>>2);
        g_bcat[tid0] = dir ? bb[j] : bf[j];
    }
    if(tid0 < HH*HH){
        int n = tid0 & (HH-1); int k = tid0 >> 9;
        g_WdecT[k*HH + n] = W_dec[n*HH + k];
    }
}

// ---------------- enc_proj GEMM (fp32 out) --------------------------------------
__global__ void k_enc_gemm(const float* __restrict__ A, const float* __restrict__ Bm,
                           const float* __restrict__ bias){
    __shared__ float As[16][68];
    __shared__ float Bs[16][68];
    const int Kk = DD, Nn = HH;
    int n0 = blockIdx.x*64, m0 = blockIdx.y*64;
    int tid = threadIdx.x;
    int tm = tid>>4, tn = tid&15;
    float acc[4][4];
    #pragma unroll
    for(int i=0;i<4;i++)
        #pragma unroll
        for(int j=0;j<4;j++) acc[i][j] = bias[n0 + tn*4 + j];

    int lrow = tid>>2, lkq = (tid&3)*4;
    for(int k0=0;k0<Kk;k0+=16){
        float4 av = *(const float4*)&A[(long)(m0+lrow)*Kk + k0 + lkq];
        float4 bv = *(const float4*)&Bm[(long)(n0+lrow)*Kk + k0 + lkq];
        __syncthreads();
        As[lkq+0][lrow]=av.x; As[lkq+1][lrow]=av.y; As[lkq+2][lrow]=av.z; As[lkq+3][lrow]=av.w;
        Bs[lkq+0][lrow]=bv.x; Bs[lkq+1][lrow]=bv.y; Bs[lkq+2][lrow]=bv.z; Bs[lkq+3][lrow]=bv.w;
        __syncthreads();
        #pragma unroll
        for(int kk=0;kk<16;kk++){
            float4 a4 = *(const float4*)&As[kk][tm*4];
            float4 b4 = *(const float4*)&Bs[kk][tn*4];
            float aa[4] = {a4.x,a4.y,a4.z,a4.w};
            float bb4[4] = {b4.x,b4.y,b4.z,b4.w};
            #pragma unroll
            for(int i=0;i<4;i++)
                #pragma unroll
                for(int j=0;j<4;j++) acc[i][j] += aa[i]*bb4[j];
        }
    }
    #pragma unroll
    for(int i=0;i<4;i++)
        #pragma unroll
        for(int j=0;j<4;j++)
            g_enc[(long)(m0+tm*4+i)*Nn + n0 + tn*4 + j] = acc[i][j];
}

// ---------------- persistent recurrent kernel: 2 domains x 512 threads ----------
union SH {
    struct { float d0[HH], vs[HH];
             float sw0[128];
             float red0[4], red1[4]; } a;                            // ~4.6KB
    struct { uint32_t Ap[8192]; float zinv[32]; } c;                 // 32.1KB
    struct { float Hs[32][64]; float Ws[64][32]; } e;                // 16KB
};

__global__ void __launch_bounds__(512, 2)
k_persist(const float* __restrict__ x, const float* __restrict__ v,
          const float* __restrict__ b_dec, int NSM){
    __shared__ SH sh;
    const int tid = threadIdx.x;
    const int lane = tid & 31, warp = tid >> 5;
    const int dom = (blockIdx.x >= NSM) ? 1 : 0;      // 0=fwd, 1=bwd
    const int dbid = blockIdx.x - dom*NSM;
    unsigned int bt = (unsigned)NSM;

    for(int s=0; s<TT; s++){
        const int t_cur = dom ? (TT-1-s) : s;

        // ======== Phase AB: scores + stale-max softmax + unnormalized ctx =======
        for(int task = dbid; task < 128; task += NSM){
            int b = task >> 2, tp = task & 3;
            int t0 = tp*128;
            {
                float a0=0.f;
                #pragma unroll
                for(int kc=0;kc<8;kc++)
                    a0 += g_decp[((kc*2+dom)*BB + b)*HH + tid];
                sh.a.d0[tid]=a0; sh.a.vs[tid]=v[tid];
            }
            __syncthreads();
            #pragma unroll 1
            for(int i=0;i<8;i++){
                int tl = warp*8 + i;
                const float* e = &g_enc[(b*TT + t0 + tl)*HH];
                float s0=0.f;
                #pragma unroll
                for(int j=0;j<16;j++){
                    int h = lane + j*32;
                    s0 += sh.a.vs[h]*fast_tanh(e[h] + sh.a.d0[h]);
                }
                s0 = warpSum(s0);
                if(lane==0) sh.a.sw0[tl] = s0;
            }
            __syncthreads();
            const float* mpr = g_mp + (s&1)*256;
            float m0 = mpr[(0*2+dom)*BB+b];
            #pragma unroll
            for(int p=1;p<4;p++) m0 = fmaxf(m0, mpr[(p*2+dom)*BB+b]);
            if(tid < 128){
                float sc = sh.a.sw0[tid];
                float e = __expf(sc - m0);
                sh.a.sw0[tid] = e;
                float z = warpSum(e);
                float mx = warpMax(sc);
                if(lane==0){ sh.a.red0[warp] = z; sh.a.red1[warp] = mx; }
            }
            __syncthreads();
            if(tid == 0){
                g_zp[(tp*2+dom)*BB+b] = sh.a.red0[0]+sh.a.red0[1]+sh.a.red0[2]+sh.a.red0[3];
                g_mp[((s+1)&1)*256 + (tp*2+dom)*BB+b] =
                    fmaxf(fmaxf(sh.a.red1[0],sh.a.red1[1]),
                          fmaxf(sh.a.red1[2],sh.a.red1[3]));
            }
            __syncthreads();
            if(tid < 384){
                const __half2* xb = (const __half2*)&g_xh[(long)(b*TT + t0)*DD] + tid;
                float a0x=0.f, a0y=0.f;
                #pragma unroll 8
                for(int t=0;t<128;t++){
                    float ww0 = sh.a.sw0[t];
                    float2 xv = __half22float2(xb[(long)t*384]);
                    a0x += ww0*xv.x; a0y += ww0*xv.y;
                }
                *(float2*)&g_ctxp[((tp*2+dom)*BB + b)*DD + tid*2] = make_float2(a0x, a0y);
            }
            __syncthreads();
        }
        gbar(dom, bt); bt += NSM;

        // ======== Phase C: gates GEMM via fp16 mma (128 tasks: nt16 x kc8) ======
        for(int task = dbid; task < 128; task += NSM){
            int nt = task & 15, kc = task >> 4;
            int n0 = nt*128, k0 = kc*256;

            __syncthreads();
            if(tid < 32){
                float z = g_zp[(0*2+dom)*BB+tid] + g_zp[(1*2+dom)*BB+tid]
                        + g_zp[(2*2+dom)*BB+tid] + g_zp[(3*2+dom)*BB+tid];
                sh.c.zinv[tid] = 1.0f / z;
            }
            __syncthreads();
            // ---- fill frag-packed A (32b x 256k, fp16 pairs) ----
            #pragma unroll
            for(int r=0;r<8;r++){
                int idx = tid + (r<<9);
                int b = idx>>7, kp = idx&127;
                int k = k0 + kp*2;
                float v0, v1;
                if(kc < 3){
                    float zi = sh.c.zinv[b];
                    v0 = (g_ctxp[((0*2+dom)*BB+b)*DD + k]
                        + g_ctxp[((1*2+dom)*BB+b)*DD + k]
                        + g_ctxp[((2*2+dom)*BB+b)*DD + k]
                        + g_ctxp[((3*2+dom)*BB+b)*DD + k]) * zi;
                    v1 = (g_ctxp[((0*2+dom)*BB+b)*DD + k+1]
                        + g_ctxp[((1*2+dom)*BB+b)*DD + k+1]
                        + g_ctxp[((2*2+dom)*BB+b)*DD + k+1]
                        + g_ctxp[((3*2+dom)*BB+b)*DD + k+1]) * zi;
                } else if(kc < 6){
                    v0 = __half2float(g_xh[(long)(b*TT + t_cur)*DD + (k-768)]);
                    v1 = __half2float(g_xh[(long)(b*TT + t_cur)*DD + (k+1-768)]);
                } else {
                    v0 = g_h[(dom*BB+b)*HH + (k-1536)];
                    v1 = g_h[(dom*BB+b)*HH + (k+1-1536)];
                }
                __half2 hv = __floats2half2_rn(v0, v1);
                int ks = kp>>3, kkp = kp&7;
                int tq = kkp&3, khalf = kkp>>2;
                int mt = b>>4, rin = b&15, gq = rin&7, hi = rin>>3;
                sh.c.Ap[(((ks*2+mt)*32 + gq*4 + tq)<<2) + khalf*2 + hi] = *(uint32_t*)&hv;
            }
            __syncthreads();

            int nw = warp>>1, kh = warp&1;     // 8 n-warps x 2 k-halves
            float acc[2][2][4];
            #pragma unroll
            for(int mt=0;mt<2;mt++)
                #pragma unroll
                for(int j=0;j<2;j++)
                    #pragma unroll
                    for(int r=0;r<4;r++) acc[mt][j][r]=0.f;

            const uint2* Bp = g_WcatPh + ((size_t)dom*128*256*32);

            #pragma unroll
            for(int i8=0;i8<8;i8++){
                int ksg = (kh<<3) + i8;
                uint4 A0 = *(const uint4*)&sh.c.Ap[((ksg*2+0)*32 + lane)*4];
                uint4 A1 = *(const uint4*)&sh.c.Ap[((ksg*2+1)*32 + lane)*4];
                int k16g = (kc<<4) + ksg;
                #pragma unroll
                for(int j=0;j<2;j++){
                    int n8g = (nt<<4) + (nw<<1) + j;
                    uint2 bb2 = Bp[((size_t)k16g*256 + n8g)*32 + lane];
                    mma_f16(acc[0][j], (const uint32_t*)&A0, bb2.x, bb2.y);
                    mma_f16(acc[1][j], (const uint32_t*)&A1, bb2.x, bb2.y);
                }
            }
            __syncthreads();
            float* buf = (float*)sh.c.Ap;
            if(kh == 1){
                #pragma unroll
                for(int mt=0;mt<2;mt++)
                    #pragma unroll
                    for(int j=0;j<2;j++)
                        #pragma unroll
                        for(int r=0;r<4;r++)
                            buf[nw*512 + (mt*2+j)*128 + r*32 + lane] = acc[mt][j][r];
            }
            __syncthreads();
            if(kh == 0){
                int gid = lane>>2, tg = lane&3;
                #pragma unroll
                for(int mt=0;mt<2;mt++){
                    #pragma unroll
                    for(int j=0;j<2;j++){
                        const float* bb4 = &buf[nw*512 + (mt*2+j)*128];
                        float c0 = acc[mt][j][0] + bb4[0*32 + lane];
                        float c1 = acc[mt][j][1] + bb4[1*32 + lane];
                        float c2 = acc[mt][j][2] + bb4[2*32 + lane];
                        float c3 = acc[mt][j][3] + bb4[3*32 + lane];
                        int n = n0 + ((nw<<1)+j)*8 + (tg<<1);
                        int br = (mt<<4) + gid;
                        *(float2*)&g_gpart[((long)(kc*2+dom)*BB + br)*N4H + n]     = make_float2(c0,c1);
                        *(float2*)&g_gpart[((long)(kc*2+dom)*BB + br + 8)*N4H + n] = make_float2(c2,c3);
                    }
                }
            }
            __syncthreads();
        }
        gbar(dom, bt); bt += NSM;

        // ======== Phase D: LSTM pointwise (grid-strided over domain) ============
        for(int idx = dbid*512 + tid; idx < BB*HH; idx += NSM*512){
            int hc = idx & (HH-1);
            int b  = idx>>9;
            float4 gs = make_float4(0.f,0.f,0.f,0.f);
            #pragma unroll
            for(int p=0;p<8;p++){
                float4 gp = *(const float4*)&g_gpart[((long)(p*2+dom)*BB + b)*N4H + hc*4];
                gs.x+=gp.x; gs.y+=gp.y; gs.z+=gp.z; gs.w+=gp.w;
            }
            float4 bc = *(const float4*)&g_bcat[dom*N4H + hc*4];
            float ig = sigm(gs.x+bc.x);
            float fg = sigm(gs.y+bc.y);
            float gg = tanh_acc(gs.z+bc.z);
            float og = sigm(gs.w+bc.w);
            int ix = (dom*BB+b)*HH + hc;
            float c = fg*g_c[ix] + ig*gg;
            float h = og*tanh_acc(c);
            g_c[ix]=c; g_h[ix]=h;
            g_hs[((dom*TT+t_cur)*BB + b)*HH + hc] = h;
        }
        gbar(dom, bt); bt += NSM;

        // ======== Phase E: dec partials (h @ WdecT), 128 tasks: nt16 x kc8 ======
        for(int task = dbid; task < 128; task += NSM){
            int nt = task & 15, kc = task >> 4;
            int n0 = nt*32, k0 = kc*64;
            #pragma unroll
            for(int r=0;r<4;r++){
                int lin = tid + 512*r;
                int bi = lin>>6, k = lin&63;
                sh.e.Hs[bi][k] = g_h[(dom*BB+bi)*HH + k0 + k];
            }
            #pragma unroll
            for(int r=0;r<4;r++){
                int lin = tid + 512*r;
                int k = lin>>5, n = lin&31;
                sh.e.Ws[k][n] = g_WdecT[(k0+k)*HH + n0 + n];
            }
            __syncthreads();
            int tb = tid>>4, tn = tid&15;
            float acc0=0.f, acc1=0.f;
            #pragma unroll 8
            for(int k=0;k<64;k++){
                float a = sh.e.Hs[tb][k];
                float2 w2 = *(const float2*)&sh.e.Ws[k][tn*2];
                acc0 += a*w2.x; acc1 += a*w2.y;
            }
            int n = n0 + tn*2;
            float bias0 = (kc==0) ? b_dec[n]   : 0.f;
            float bias1 = (kc==0) ? b_dec[n+1] : 0.f;
            g_decp[((kc*2+dom)*BB + tb)*HH + n]   = acc0 + bias0;
            g_decp[((kc*2+dom)*BB + tb)*HH + n+1] = acc1 + bias1;
            __syncthreads();
        }
        gbar(dom, bt); bt += NSM;
    }
}

// ---------------- final head ----------------------------------------------------
__global__ void k_head(const float* __restrict__ W_head, const float* __restrict__ b_head,
                       float* __restrict__ out){
    __shared__ float Ws[CC*2*HH];   // 28KB
    int tid = threadIdx.x;
    for(int i=tid;i<CC*2*HH;i+=256) Ws[i] = W_head[i];
    __syncthreads();
    int warp = tid>>5, lane = tid&31;
    int m = blockIdx.x*8 + warp;
    int b = m >> 9, t = m & (TT-1);
    const float* hf = &g_hs[((0*TT+t)*BB + b)*HH];
    const float* hb = &g_hs[((1*TT+t)*BB + b)*HH];
    float acc[CC];
    #pragma unroll
    for(int c=0;c<CC;c++) acc[c]=0.f;
    #pragma unroll 4
    for(int i=0;i<16;i++){
        int k = lane + i*32;
        float vf = hf[k];
        float vb = hb[k];
        #pragma unroll
        for(int c=0;c<CC;c++){
            acc[c] += vf*Ws[c*1024 + k] + vb*Ws[c*1024 + 512 + k];
        }
    }
    float res = 0.f;
    #pragma unroll
    for(int c=0;c<CC;c++){
        float r = warpSum(acc[c]);
        if(lane==c) res = r;
    }
    if(lane < CC) out[m*CC + lane] = res + b_head[lane];
}

// ---------------- launch ----------------
extern "C" void kernel_launch(void* const* d_in, const int* in_sizes, int n_in,
                              void* d_out, int out_size){
    const float* x      = (const float*)d_in[0];
    const float* Wf_ih  = (const float*)d_in[1];
    const float* Wf_hh  = (const float*)d_in[2];
    const float* bf     = (const float*)d_in[3];
    const float* Wb_ih  = (const float*)d_in[4];
    const float* Wb_hh  = (const float*)d_in[5];
    const float* bb     = (const float*)d_in[6];
    const float* W_enc  = (const float*)d_in[7];
    const float* b_enc  = (const float*)d_in[8];
    const float* W_dec  = (const float*)d_in[9];
    const float* b_dec  = (const float*)d_in[10];
    const float* v      = (const float*)d_in[11];
    const float* W_head = (const float*)d_in[12];
    const float* b_head = (const float*)d_in[13];
    float* out = (float*)d_out;

    int dev = 0;
    cudaGetDevice(&dev);
    int nsm = 128;
    cudaDeviceGetAttribute(&nsm, cudaDevAttrMultiProcessorCount, dev);

    k_init<<<1024, 256>>>(b_dec);
    k_prep<<<2048, 256>>>(Wf_ih, Wf_hh, bf, Wb_ih, Wb_hh, bb, W_dec, x);
    k_enc_gemm<<<dim3(8, 256), 256>>>(x, W_enc, b_enc);
    k_persist<<<2*nsm, 512>>>(x, v, b_dec, nsm);
    k_head<<<2048, 256>>>(W_head, b_head, out);
}